// round 1
// baseline (speedup 1.0000x reference)
#include <cuda_runtime.h>
#include <math.h>

#define BATCH 16
#define HDIM 128
#define WDIM 128
#define HID 64

// ping-pong activation buffers (NHWC), 64MB each
__device__ __align__(16) float g_buf0[BATCH * HDIM * WDIM * HID];
__device__ __align__(16) float g_buf1[BATCH * HDIM * WDIM * HID];
// repacked layer-1 weights: [cp(32)][k(576)][12]  (5 gates x 2 channels + 2 pad)
__device__ __align__(16) float g_w1p[32 * 576 * 12];

__device__ __forceinline__ float sigm(float v) { return 1.0f / (1.0f + expf(-v)); }

// ---------------------------------------------------------------------------
// Repack layer-1 weights: gates {ci, co, cg, px, py} for channel pair cp.
// conv_w1: [256][128][3][3] (only first 64 in-ch used since h=0)
// ---------------------------------------------------------------------------
__global__ void repack_w1(const float* __restrict__ cw,
                          const float* __restrict__ pxw,
                          const float* __restrict__ pyw) {
    int idx = blockIdx.x * 256 + threadIdx.x;   // cp*576 + k
    if (idx >= 32 * 576) return;
    int cp = idx / 576, k = idx % 576;
    int tap = k >> 6, cin = k & 63;
    float* dst = g_w1p + idx * 12;
#pragma unroll
    for (int j = 0; j < 2; j++) {
        int c = cp * 2 + j;
        dst[j * 5 + 0] = cw[((c) * 128 + cin) * 9 + tap];        // ci
        dst[j * 5 + 1] = cw[((128 + c) * 128 + cin) * 9 + tap];  // co
        dst[j * 5 + 2] = cw[((192 + c) * 128 + cin) * 9 + tap];  // cg
        dst[j * 5 + 3] = pxw[(c * 64 + cin) * 9 + tap];          // px
        dst[j * 5 + 4] = pyw[(c * 64 + cin) * 9 + tap];          // py
    }
    dst[10] = 0.0f; dst[11] = 0.0f;
}

// ---------------------------------------------------------------------------
// Layer 0 fused gates: CIN=1. Each thread = one pixel, loops 64 channels.
// Writes h (pre-attention) to g_buf0, NHWC.
// conv_w0: [256][65][3][3] -> only ic=0 used: flat oc*585 + tap
// ---------------------------------------------------------------------------
__global__ __launch_bounds__(256) void layer0_gates(
    const float* __restrict__ x, const float* __restrict__ cw,
    const float* __restrict__ cb, const float* __restrict__ pxw,
    const float* __restrict__ pyw) {
    __shared__ float s_w[5][64][9];
    __shared__ float s_b[3][64];
    int tid = threadIdx.x;
    for (int i = tid; i < 576; i += 256) {
        int c = i / 9, j = i % 9;
        s_w[0][c][j] = cw[c * 585 + j];
        s_w[1][c][j] = cw[(128 + c) * 585 + j];
        s_w[2][c][j] = cw[(192 + c) * 585 + j];
        s_w[3][c][j] = pxw[i];
        s_w[4][c][j] = pyw[i];
    }
    if (tid < 64) {
        s_b[0][tid] = cb[tid];
        s_b[1][tid] = cb[128 + tid];
        s_b[2][tid] = cb[192 + tid];
    }
    __syncthreads();

    int p = blockIdx.x * 256 + tid;                 // pixel id [0, 262144)
    int b = p >> 14, y = (p >> 7) & 127, xc = p & 127;
    float pv[9];
#pragma unroll
    for (int ky = 0; ky < 3; ky++)
#pragma unroll
        for (int kx = 0; kx < 3; kx++) {
            int gy = y + ky - 1, gx = xc + kx - 1;
            pv[ky * 3 + kx] = (gy >= 0 && gy < 128 && gx >= 0 && gx < 128)
                                  ? x[(b << 14) + gy * 128 + gx] : 0.0f;
        }
    float* outp = g_buf0 + (p << 6);
    for (int c = 0; c < 64; c++) {
        float aci = 0.f, aco = 0.f, acg = 0.f, apx = 0.f, apy = 0.f;
#pragma unroll
        for (int j = 0; j < 9; j++) {
            float a = pv[j];
            aci += a * s_w[0][c][j];
            aco += a * s_w[1][c][j];
            acg += a * s_w[2][c][j];
            apx += a * s_w[3][c][j];
            apy += a * s_w[4][c][j];
        }
        float ig = sigm(aci + apx + s_b[0][c]);
        float og = sigm(aco + apy + s_b[1][c]);
        float gg = tanhf(acg + apy + s_b[2][c]);
        outp[c] = og * tanhf(ig * gg);
    }
}

// ---------------------------------------------------------------------------
// Window attention: one block per 8x8 window (4096 blocks).
// Reads g_buf0, writes g_buf1 (NHWC). T=64 tokens, C=64, 4 heads of dim 16.
// Dynamic smem: x/q/k/v, each [64][68] floats (pad 68 keeps 16B alignment).
// ---------------------------------------------------------------------------
__global__ __launch_bounds__(256) void win_attn(
    const float* __restrict__ qkvw, const float* __restrict__ projw,
    const float* __restrict__ projb) {
    extern __shared__ float sm[];
    float* s_in = sm;                 // [64][68]  x, later o
    float* s_q = sm + 64 * 68;
    float* s_k = s_q + 64 * 68;
    float* s_v = s_k + 64 * 68;
    int tid = threadIdx.x;
    int wid = blockIdx.x;
    int b = wid >> 8, wy = (wid >> 4) & 15, wx = wid & 15;
    int base = ((b * 128 + wy * 8) * 128 + wx * 8) * 64;

    for (int i = tid; i < 4096; i += 256) {
        int t = i >> 6, c = i & 63;
        int ty = t >> 3, tx = t & 7;
        s_in[t * 68 + c] = g_buf0[base + (ty * 128 + tx) * 64 + c];
    }
    __syncthreads();

    // ---- QKV: 16 token-groups x 16 row-groups, thread tile 4 tokens x 12 rows
    {
        int tt = tid & 15, tr = tid >> 4;
        int t0 = tt * 4, r0 = tr * 12;
        float acc[12][4];
#pragma unroll
        for (int j = 0; j < 12; j++)
#pragma unroll
            for (int i2 = 0; i2 < 4; i2++) acc[j][i2] = 0.0f;
        for (int c = 0; c < 64; c += 4) {
            float4 a[4];
#pragma unroll
            for (int i2 = 0; i2 < 4; i2++)
                a[i2] = *(const float4*)(s_in + (t0 + i2) * 68 + c);
#pragma unroll
            for (int j = 0; j < 12; j++) {
                float4 w = __ldg((const float4*)(qkvw + (r0 + j) * 64 + c));
#pragma unroll
                for (int i2 = 0; i2 < 4; i2++)
                    acc[j][i2] += w.x * a[i2].x + w.y * a[i2].y +
                                  w.z * a[i2].z + w.w * a[i2].w;
            }
        }
#pragma unroll
        for (int j = 0; j < 12; j++) {
            int r = r0 + j;
            float* dst; float scl = 1.0f; int rr;
            if (r < 64)       { dst = s_q; rr = r;       scl = 0.25f; } // HD^-0.5
            else if (r < 128) { dst = s_k; rr = r - 64; }
            else              { dst = s_v; rr = r - 128; }
#pragma unroll
            for (int i2 = 0; i2 < 4; i2++)
                dst[(t0 + i2) * 68 + rr] = acc[j][i2] * scl;
        }
    }
    __syncthreads();

    // ---- attention: thread = (head, query); scores fully in registers
    {
        int h = tid >> 6, qi = tid & 63;
        int d0 = h * 16;
        float qv[16];
#pragma unroll
        for (int d4 = 0; d4 < 4; d4++) {
            float4 q4 = *(const float4*)(s_q + qi * 68 + d0 + d4 * 4);
            qv[d4 * 4 + 0] = q4.x; qv[d4 * 4 + 1] = q4.y;
            qv[d4 * 4 + 2] = q4.z; qv[d4 * 4 + 3] = q4.w;
        }
        float scv[64];
#pragma unroll
        for (int kj = 0; kj < 64; kj++) {
            const float* kp = s_k + kj * 68 + d0;
            float s = 0.0f;
#pragma unroll
            for (int d4 = 0; d4 < 4; d4++) {
                float4 k4 = *(const float4*)(kp + d4 * 4);
                s += qv[d4 * 4 + 0] * k4.x + qv[d4 * 4 + 1] * k4.y +
                     qv[d4 * 4 + 2] * k4.z + qv[d4 * 4 + 3] * k4.w;
            }
            scv[kj] = s;
        }
        float m = scv[0];
#pragma unroll
        for (int kj = 1; kj < 64; kj++) m = fmaxf(m, scv[kj]);
        float sum = 0.0f;
#pragma unroll
        for (int kj = 0; kj < 64; kj++) { scv[kj] = __expf(scv[kj] - m); sum += scv[kj]; }
        float ov[16];
#pragma unroll
        for (int d = 0; d < 16; d++) ov[d] = 0.0f;
#pragma unroll
        for (int kj = 0; kj < 64; kj++) {
            const float* vp = s_v + kj * 68 + d0;
            float pp = scv[kj];
#pragma unroll
            for (int d4 = 0; d4 < 4; d4++) {
                float4 v4 = *(const float4*)(vp + d4 * 4);
                ov[d4 * 4 + 0] += pp * v4.x; ov[d4 * 4 + 1] += pp * v4.y;
                ov[d4 * 4 + 2] += pp * v4.z; ov[d4 * 4 + 3] += pp * v4.w;
            }
        }
        float inv = 1.0f / sum;
#pragma unroll
        for (int d = 0; d < 16; d++) s_in[qi * 68 + d0 + d] = ov[d] * inv;
    }
    __syncthreads();

    // ---- proj: out = o @ proj_w.T + b; thread tile 4 tokens x 4 channels
    {
        int tt = tid & 15, tc = tid >> 4;
        int t0 = tt * 4, c0 = tc * 4;
        float acc[4][4];
#pragma unroll
        for (int j = 0; j < 4; j++)
#pragma unroll
            for (int i2 = 0; i2 < 4; i2++) acc[j][i2] = 0.0f;
        for (int k = 0; k < 64; k += 4) {
            float4 a[4];
#pragma unroll
            for (int i2 = 0; i2 < 4; i2++)
                a[i2] = *(const float4*)(s_in + (t0 + i2) * 68 + k);
#pragma unroll
            for (int j = 0; j < 4; j++) {
                float4 w = __ldg((const float4*)(projw + (c0 + j) * 64 + k));
#pragma unroll
                for (int i2 = 0; i2 < 4; i2++)
                    acc[j][i2] += w.x * a[i2].x + w.y * a[i2].y +
                                  w.z * a[i2].z + w.w * a[i2].w;
            }
        }
#pragma unroll
        for (int i2 = 0; i2 < 4; i2++) {
            int t = t0 + i2;
            int ty = t >> 3, tx = t & 7;
            int oidx = base + (ty * 128 + tx) * 64 + c0;
#pragma unroll
            for (int j = 0; j < 4; j++)
                g_buf1[oidx + j] = acc[j][i2] + __ldg(projb + c0 + j);
        }
    }
}

// ---------------------------------------------------------------------------
// Layer 1 fused gates: the 97-GFLOP conv. 8x16 spatial tile per block,
// input halo staged [cin][10][18] in smem, weights from g_w1p via uniform
// vectorized LDG. Thread tile: 4 pixels x 2 channels x 5 gates = 40 accs.
// Reads g_buf1 (layer-0 attention out), writes g_buf0.
// ---------------------------------------------------------------------------
#define TILE_IN (64 * 10 * 18)
__global__ __launch_bounds__(256) void layer1_gates(const float* __restrict__ cb) {
    __shared__ float s_in[TILE_IN];   // [c][yy][xx] = c*180 + yy*18 + xx
    int tile = blockIdx.x;            // 2048 = 16b x 16 tile-rows x 8 tile-cols
    int b = tile >> 7;
    int trow = (tile >> 3) & 15;
    int tcol = tile & 7;
    int y0 = trow * 8, x0 = tcol * 16;
    int tid = threadIdx.x;

    for (int i = tid; i < TILE_IN; i += 256) {
        int pos = i >> 6, c = i & 63;
        int yy = pos / 18, xx = pos % 18;
        int gy = y0 + yy - 1, gx = x0 + xx - 1;
        float v = 0.0f;
        if (gy >= 0 && gy < 128 && gx >= 0 && gx < 128)
            v = g_buf1[(((b << 7) + gy) * 128 + gx) * 64 + c];
        s_in[c * 180 + pos] = v;
    }
    __syncthreads();

    int pg = tid & 31, cg = tid >> 5;
    int py0 = pg >> 4;            // 0 or 1; thread pixels: rows py0+2i, col px
    int px = pg & 15;

    for (int chunk = 0; chunk < 4; chunk++) {
        int cp = chunk * 8 + cg;                        // channel pair id
        const float4* wrow = (const float4*)(g_w1p + cp * 576 * 12);
        float acc[4][10];
#pragma unroll
        for (int i = 0; i < 4; i++)
#pragma unroll
            for (int g = 0; g < 10; g++) acc[i][g] = 0.0f;

#pragma unroll 1
        for (int ky = 0; ky < 3; ky++) {
#pragma unroll 1
            for (int kx = 0; kx < 3; kx++) {
                const float* sp = s_in + (py0 + ky) * 18 + px + kx;
                int kbase = (ky * 3 + kx) * 64;
#pragma unroll 2
                for (int cin = 0; cin < 64; cin++) {
                    const float4* wp4 = wrow + (kbase + cin) * 3;
                    float4 w0 = __ldg(wp4), w1 = __ldg(wp4 + 1), w2 = __ldg(wp4 + 2);
                    float wv[10] = {w0.x, w0.y, w0.z, w0.w,
                                    w1.x, w1.y, w1.z, w1.w, w2.x, w2.y};
                    const float* spc = sp + cin * 180;
                    float av[4] = {spc[0], spc[36], spc[72], spc[108]};
#pragma unroll
                    for (int i = 0; i < 4; i++)
#pragma unroll
                        for (int g = 0; g < 10; g++) acc[i][g] += av[i] * wv[g];
                }
            }
        }
        // fused gate epilogue
#pragma unroll
        for (int j = 0; j < 2; j++) {
            int c = cp * 2 + j;
            float bci = __ldg(cb + c), bco = __ldg(cb + 128 + c),
                  bcg = __ldg(cb + 192 + c);
#pragma unroll
            for (int i = 0; i < 4; i++) {
                float ci = acc[i][j * 5 + 0], co = acc[i][j * 5 + 1];
                float cgv = acc[i][j * 5 + 2], pxv = acc[i][j * 5 + 3];
                float pyv = acc[i][j * 5 + 4];
                float ig = sigm(ci + pxv + bci);
                float og = sigm(co + pyv + bco);
                float gg = tanhf(cgv + pyv + bcg);
                int gy = y0 + py0 + 2 * i, gx = x0 + px;
                g_buf0[(((b << 7) + gy) * 128 + gx) * 64 + c] = og * tanhf(ig * gg);
            }
        }
    }
}

// ---------------------------------------------------------------------------
// Output 1x1 conv: out[p] = dot64(h1[p], out_w) + out_b
// ---------------------------------------------------------------------------
__global__ __launch_bounds__(256) void out_conv(const float* __restrict__ ow,
                                                const float* __restrict__ ob,
                                                float* __restrict__ out) {
    int p = blockIdx.x * 256 + threadIdx.x;
    const float4* hv = (const float4*)(g_buf1 + (p << 6));
    float acc = 0.0f;
#pragma unroll
    for (int k = 0; k < 16; k++) {
        float4 a = hv[k];
        float4 w = __ldg(((const float4*)ow) + k);
        acc += a.x * w.x + a.y * w.y + a.z * w.z + a.w * w.w;
    }
    out[p] = acc + __ldg(ob);
}

// ---------------------------------------------------------------------------
extern "C" void kernel_launch(void* const* d_in, const int* in_sizes, int n_in,
                              void* d_out, int out_size) {
    const float* x      = (const float*)d_in[0];
    const float* cw0    = (const float*)d_in[1];
    const float* cb0    = (const float*)d_in[2];
    const float* pxw0   = (const float*)d_in[3];
    const float* pyw0   = (const float*)d_in[4];
    const float* qkvw0  = (const float*)d_in[5];
    const float* projw0 = (const float*)d_in[6];
    const float* projb0 = (const float*)d_in[7];
    const float* cw1    = (const float*)d_in[8];
    const float* cb1    = (const float*)d_in[9];
    const float* pxw1   = (const float*)d_in[10];
    const float* pyw1   = (const float*)d_in[11];
    const float* qkvw1  = (const float*)d_in[12];
    const float* projw1 = (const float*)d_in[13];
    const float* projb1 = (const float*)d_in[14];
    const float* outw   = (const float*)d_in[15];
    const float* outb   = (const float*)d_in[16];
    float* out = (float*)d_out;

    const int attn_smem = 4 * 64 * 68 * sizeof(float);  // 69632 B
    cudaFuncSetAttribute(win_attn, cudaFuncAttributeMaxDynamicSharedMemorySize,
                         attn_smem);

    repack_w1<<<72, 256>>>(cw1, pxw1, pyw1);
    layer0_gates<<<1024, 256>>>(x, cw0, cb0, pxw0, pyw0);          // -> buf0
    win_attn<<<4096, 256, attn_smem>>>(qkvw0, projw0, projb0);     // buf0 -> buf1
    layer1_gates<<<2048, 256>>>(cb1);                              // buf1 -> buf0
    win_attn<<<4096, 256, attn_smem>>>(qkvw1, projw1, projb1);     // buf0 -> buf1
    out_conv<<<1024, 256>>>(outw, outb, out);                      // buf1 -> d_out
}

// round 2
// speedup vs baseline: 1.1238x; 1.1238x over previous
#include <cuda_runtime.h>
#include <math.h>

#define BATCH 16
#define HDIM 128
#define WDIM 128
#define HID 64

// ping-pong activation buffers (NHWC), 64MB each
__device__ __align__(16) float g_buf0[BATCH * HDIM * WDIM * HID];
__device__ __align__(16) float g_buf1[BATCH * HDIM * WDIM * HID];
// repacked layer-1 weights: [cp(32)][cin(64)*9+tap][12] (5 gates x 2 ch + pad)
__device__ __align__(16) float g_w1p[32 * 576 * 12];

__device__ __forceinline__ float sigm(float v) { return 1.0f / (1.0f + expf(-v)); }

// ---------------------------------------------------------------------------
// Repack layer-1 weights: gates {ci, co, cg, px, py} for channel pair cp.
// conv_w1: [256][128][3][3] (only first 64 in-ch used since h=0)
// New order: k = cin*9 + tap  (cin-major for streaming in the cin-outer loop)
// ---------------------------------------------------------------------------
__global__ void repack_w1(const float* __restrict__ cw,
                          const float* __restrict__ pxw,
                          const float* __restrict__ pyw) {
    int idx = blockIdx.x * 256 + threadIdx.x;   // cp*576 + k
    if (idx >= 32 * 576) return;
    int cp = idx / 576, k = idx % 576;
    int cin = k / 9, tap = k % 9;
    float* dst = g_w1p + idx * 12;
#pragma unroll
    for (int j = 0; j < 2; j++) {
        int c = cp * 2 + j;
        dst[j * 5 + 0] = cw[((c) * 128 + cin) * 9 + tap];        // ci
        dst[j * 5 + 1] = cw[((128 + c) * 128 + cin) * 9 + tap];  // co
        dst[j * 5 + 2] = cw[((192 + c) * 128 + cin) * 9 + tap];  // cg
        dst[j * 5 + 3] = pxw[(c * 64 + cin) * 9 + tap];          // px
        dst[j * 5 + 4] = pyw[(c * 64 + cin) * 9 + tap];          // py
    }
    dst[10] = 0.0f; dst[11] = 0.0f;
}

// ---------------------------------------------------------------------------
// Layer 0 fused gates: CIN=1. Each thread = one pixel, loops 64 channels.
// Writes h (pre-attention) to g_buf0, NHWC.
// conv_w0: [256][65][3][3] -> only ic=0 used: flat oc*585 + tap
// ---------------------------------------------------------------------------
__global__ __launch_bounds__(256) void layer0_gates(
    const float* __restrict__ x, const float* __restrict__ cw,
    const float* __restrict__ cb, const float* __restrict__ pxw,
    const float* __restrict__ pyw) {
    __shared__ float s_w[5][64][9];
    __shared__ float s_b[3][64];
    int tid = threadIdx.x;
    for (int i = tid; i < 576; i += 256) {
        int c = i / 9, j = i % 9;
        s_w[0][c][j] = cw[c * 585 + j];
        s_w[1][c][j] = cw[(128 + c) * 585 + j];
        s_w[2][c][j] = cw[(192 + c) * 585 + j];
        s_w[3][c][j] = pxw[i];
        s_w[4][c][j] = pyw[i];
    }
    if (tid < 64) {
        s_b[0][tid] = cb[tid];
        s_b[1][tid] = cb[128 + tid];
        s_b[2][tid] = cb[192 + tid];
    }
    __syncthreads();

    int p = blockIdx.x * 256 + tid;                 // pixel id [0, 262144)
    int b = p >> 14, y = (p >> 7) & 127, xc = p & 127;
    float pv[9];
#pragma unroll
    for (int ky = 0; ky < 3; ky++)
#pragma unroll
        for (int kx = 0; kx < 3; kx++) {
            int gy = y + ky - 1, gx = xc + kx - 1;
            pv[ky * 3 + kx] = (gy >= 0 && gy < 128 && gx >= 0 && gx < 128)
                                  ? x[(b << 14) + gy * 128 + gx] : 0.0f;
        }
    float* outp = g_buf0 + (p << 6);
    for (int c = 0; c < 64; c++) {
        float aci = 0.f, aco = 0.f, acg = 0.f, apx = 0.f, apy = 0.f;
#pragma unroll
        for (int j = 0; j < 9; j++) {
            float a = pv[j];
            aci += a * s_w[0][c][j];
            aco += a * s_w[1][c][j];
            acg += a * s_w[2][c][j];
            apx += a * s_w[3][c][j];
            apy += a * s_w[4][c][j];
        }
        float ig = sigm(aci + apx + s_b[0][c]);
        float og = sigm(aco + apy + s_b[1][c]);
        float gg = tanhf(acg + apy + s_b[2][c]);
        outp[c] = og * tanhf(ig * gg);
    }
}

// ---------------------------------------------------------------------------
// Window attention: one block per 8x8 window (4096 blocks).
// Reads g_buf0, writes g_buf1 (NHWC). T=64 tokens, C=64, 4 heads of dim 16.
// Dynamic smem: x/q/k/v, each [64][68] floats (pad 68 keeps 16B alignment).
// ---------------------------------------------------------------------------
__global__ __launch_bounds__(256) void win_attn(
    const float* __restrict__ qkvw, const float* __restrict__ projw,
    const float* __restrict__ projb) {
    extern __shared__ float sm[];
    float* s_in = sm;                 // [64][68]  x, later o
    float* s_q = sm + 64 * 68;
    float* s_k = s_q + 64 * 68;
    float* s_v = s_k + 64 * 68;
    int tid = threadIdx.x;
    int wid = blockIdx.x;
    int b = wid >> 8, wy = (wid >> 4) & 15, wx = wid & 15;
    int base = ((b * 128 + wy * 8) * 128 + wx * 8) * 64;

    for (int i = tid; i < 4096; i += 256) {
        int t = i >> 6, c = i & 63;
        int ty = t >> 3, tx = t & 7;
        s_in[t * 68 + c] = g_buf0[base + (ty * 128 + tx) * 64 + c];
    }
    __syncthreads();

    // ---- QKV: 16 token-groups x 16 row-groups, thread tile 4 tokens x 12 rows
    {
        int tt = tid & 15, tr = tid >> 4;
        int t0 = tt * 4, r0 = tr * 12;
        float acc[12][4];
#pragma unroll
        for (int j = 0; j < 12; j++)
#pragma unroll
            for (int i2 = 0; i2 < 4; i2++) acc[j][i2] = 0.0f;
        for (int c = 0; c < 64; c += 4) {
            float4 a[4];
#pragma unroll
            for (int i2 = 0; i2 < 4; i2++)
                a[i2] = *(const float4*)(s_in + (t0 + i2) * 68 + c);
#pragma unroll
            for (int j = 0; j < 12; j++) {
                float4 w = __ldg((const float4*)(qkvw + (r0 + j) * 64 + c));
#pragma unroll
                for (int i2 = 0; i2 < 4; i2++)
                    acc[j][i2] += w.x * a[i2].x + w.y * a[i2].y +
                                  w.z * a[i2].z + w.w * a[i2].w;
            }
        }
#pragma unroll
        for (int j = 0; j < 12; j++) {
            int r = r0 + j;
            float* dst; float scl = 1.0f; int rr;
            if (r < 64)       { dst = s_q; rr = r;       scl = 0.25f; } // HD^-0.5
            else if (r < 128) { dst = s_k; rr = r - 64; }
            else              { dst = s_v; rr = r - 128; }
#pragma unroll
            for (int i2 = 0; i2 < 4; i2++)
                dst[(t0 + i2) * 68 + rr] = acc[j][i2] * scl;
        }
    }
    __syncthreads();

    // ---- attention: thread = (head, query); scores fully in registers
    {
        int h = tid >> 6, qi = tid & 63;
        int d0 = h * 16;
        float qv[16];
#pragma unroll
        for (int d4 = 0; d4 < 4; d4++) {
            float4 q4 = *(const float4*)(s_q + qi * 68 + d0 + d4 * 4);
            qv[d4 * 4 + 0] = q4.x; qv[d4 * 4 + 1] = q4.y;
            qv[d4 * 4 + 2] = q4.z; qv[d4 * 4 + 3] = q4.w;
        }
        float scv[64];
#pragma unroll
        for (int kj = 0; kj < 64; kj++) {
            const float* kp = s_k + kj * 68 + d0;
            float s = 0.0f;
#pragma unroll
            for (int d4 = 0; d4 < 4; d4++) {
                float4 k4 = *(const float4*)(kp + d4 * 4);
                s += qv[d4 * 4 + 0] * k4.x + qv[d4 * 4 + 1] * k4.y +
                     qv[d4 * 4 + 2] * k4.z + qv[d4 * 4 + 3] * k4.w;
            }
            scv[kj] = s;
        }
        float m = scv[0];
#pragma unroll
        for (int kj = 1; kj < 64; kj++) m = fmaxf(m, scv[kj]);
        float sum = 0.0f;
#pragma unroll
        for (int kj = 0; kj < 64; kj++) { scv[kj] = __expf(scv[kj] - m); sum += scv[kj]; }
        float ov[16];
#pragma unroll
        for (int d = 0; d < 16; d++) ov[d] = 0.0f;
#pragma unroll
        for (int kj = 0; kj < 64; kj++) {
            const float* vp = s_v + kj * 68 + d0;
            float pp = scv[kj];
#pragma unroll
            for (int d4 = 0; d4 < 4; d4++) {
                float4 v4 = *(const float4*)(vp + d4 * 4);
                ov[d4 * 4 + 0] += pp * v4.x; ov[d4 * 4 + 1] += pp * v4.y;
                ov[d4 * 4 + 2] += pp * v4.z; ov[d4 * 4 + 3] += pp * v4.w;
            }
        }
        float inv = 1.0f / sum;
#pragma unroll
        for (int d = 0; d < 16; d++) s_in[qi * 68 + d0 + d] = ov[d] * inv;
    }
    __syncthreads();

    // ---- proj: out = o @ proj_w.T + b; thread tile 4 tokens x 4 channels
    {
        int tt = tid & 15, tc = tid >> 4;
        int t0 = tt * 4, c0 = tc * 4;
        float acc[4][4];
#pragma unroll
        for (int j = 0; j < 4; j++)
#pragma unroll
            for (int i2 = 0; i2 < 4; i2++) acc[j][i2] = 0.0f;
        for (int k = 0; k < 64; k += 4) {
            float4 a[4];
#pragma unroll
            for (int i2 = 0; i2 < 4; i2++)
                a[i2] = *(const float4*)(s_in + (t0 + i2) * 68 + k);
#pragma unroll
            for (int j = 0; j < 4; j++) {
                float4 w = __ldg((const float4*)(projw + (c0 + j) * 64 + k));
#pragma unroll
                for (int i2 = 0; i2 < 4; i2++)
                    acc[j][i2] += w.x * a[i2].x + w.y * a[i2].y +
                                  w.z * a[i2].z + w.w * a[i2].w;
            }
        }
#pragma unroll
        for (int i2 = 0; i2 < 4; i2++) {
            int t = t0 + i2;
            int ty = t >> 3, tx = t & 7;
            int oidx = base + (ty * 128 + tx) * 64 + c0;
#pragma unroll
            for (int j = 0; j < 4; j++)
                g_buf1[oidx + j] = acc[j][i2] + __ldg(projb + c0 + j);
        }
    }
}

// ---------------------------------------------------------------------------
// Layer 1 fused gates (97 GFLOP conv), v2: column register tiling.
// Block tile: 8 rows x 16 cols of pixels. Thread: full 8-row column (px) x
// one channel pair (10 gate outputs) = 80 accumulators.
// Per cin: load 3 cols x 10 rows of acts ONCE (30 LDS), reuse across 9 taps
// -> 720 FMA per 57 L1 ops (was 40 per 7).
// smem layout: s_in[c][xx][yy], yy contiguous (10), xx stride 10, c stride 186
// (pad -> act-lane stride 10 words, gcd(10,32)=2 -> conflict-free LDS).
// Reads g_buf1 (layer-0 attention out), writes g_buf0.
// ---------------------------------------------------------------------------
#define C_STRIDE 186
__global__ __launch_bounds__(256) void layer1_gates(const float* __restrict__ cb) {
    __shared__ float s_in[64 * C_STRIDE];   // 47616 B
    int tile = blockIdx.x;            // 2048 = 16b x 16 tile-rows x 8 tile-cols
    int b = tile >> 7;
    int trow = (tile >> 3) & 15;
    int tcol = tile & 7;
    int y0 = trow * 8, x0 = tcol * 16;
    int tid = threadIdx.x;

    // halo fill: [c][xx 0..17][yy 0..9]; gy = y0+yy-1, gx = x0+xx-1
    for (int i = tid; i < 64 * 180; i += 256) {
        int c = i & 63, pos = i >> 6;
        int xx = pos / 10, yy = pos % 10;
        int gy = y0 + yy - 1, gx = x0 + xx - 1;
        float v = 0.0f;
        if (gy >= 0 && gy < 128 && gx >= 0 && gx < 128)
            v = g_buf1[(((b << 7) + gy) * 128 + gx) * 64 + c];
        s_in[c * C_STRIDE + xx * 10 + yy] = v;
    }
    __syncthreads();

    int px = tid & 15;        // pixel column 0..15
    int cg = tid >> 4;        // channel-pair slot 0..15

#pragma unroll 1
    for (int chunk = 0; chunk < 2; chunk++) {
        int cp = chunk * 16 + cg;                       // channel pair id
        const float4* wrow = (const float4*)(g_w1p + cp * 576 * 12);
        float acc[8][10];
#pragma unroll
        for (int i = 0; i < 8; i++)
#pragma unroll
            for (int g = 0; g < 10; g++) acc[i][g] = 0.0f;

#pragma unroll 1
        for (int cin = 0; cin < 64; cin++) {
            const float* sc = s_in + cin * C_STRIDE;
#pragma unroll
            for (int kx = 0; kx < 3; kx++) {
                float a[10];
                const float* col = sc + (px + kx) * 10;
#pragma unroll
                for (int r = 0; r < 10; r++) a[r] = col[r];
#pragma unroll
                for (int ky = 0; ky < 3; ky++) {
                    const float4* wp4 = wrow + (cin * 9 + ky * 3 + kx) * 3;
                    float4 w0 = __ldg(wp4), w1 = __ldg(wp4 + 1), w2 = __ldg(wp4 + 2);
                    float wv[10] = {w0.x, w0.y, w0.z, w0.w,
                                    w1.x, w1.y, w1.z, w1.w, w2.x, w2.y};
#pragma unroll
                    for (int i = 0; i < 8; i++) {
                        float av = a[i + ky];
#pragma unroll
                        for (int g = 0; g < 10; g++) acc[i][g] += av * wv[g];
                    }
                }
            }
        }
        // fused gate epilogue
#pragma unroll
        for (int j = 0; j < 2; j++) {
            int c = cp * 2 + j;
            float bci = __ldg(cb + c), bco = __ldg(cb + 128 + c),
                  bcg = __ldg(cb + 192 + c);
#pragma unroll
            for (int i = 0; i < 8; i++) {
                float ci = acc[i][j * 5 + 0], co = acc[i][j * 5 + 1];
                float cgv = acc[i][j * 5 + 2], pxv = acc[i][j * 5 + 3];
                float pyv = acc[i][j * 5 + 4];
                float ig = sigm(ci + pxv + bci);
                float og = sigm(co + pyv + bco);
                float gg = tanhf(cgv + pyv + bcg);
                int gy = y0 + i, gx = x0 + px;
                g_buf0[(((b << 7) + gy) * 128 + gx) * 64 + c] = og * tanhf(ig * gg);
            }
        }
    }
}

// ---------------------------------------------------------------------------
// Output 1x1 conv: out[p] = dot64(h1[p], out_w) + out_b
// ---------------------------------------------------------------------------
__global__ __launch_bounds__(256) void out_conv(const float* __restrict__ ow,
                                                const float* __restrict__ ob,
                                                float* __restrict__ out) {
    int p = blockIdx.x * 256 + threadIdx.x;
    const float4* hv = (const float4*)(g_buf1 + (p << 6));
    float acc = 0.0f;
#pragma unroll
    for (int k = 0; k < 16; k++) {
        float4 a = hv[k];
        float4 w = __ldg(((const float4*)ow) + k);
        acc += a.x * w.x + a.y * w.y + a.z * w.z + a.w * w.w;
    }
    out[p] = acc + __ldg(ob);
}

// ---------------------------------------------------------------------------
extern "C" void kernel_launch(void* const* d_in, const int* in_sizes, int n_in,
                              void* d_out, int out_size) {
    const float* x      = (const float*)d_in[0];
    const float* cw0    = (const float*)d_in[1];
    const float* cb0    = (const float*)d_in[2];
    const float* pxw0   = (const float*)d_in[3];
    const float* pyw0   = (const float*)d_in[4];
    const float* qkvw0  = (const float*)d_in[5];
    const float* projw0 = (const float*)d_in[6];
    const float* projb0 = (const float*)d_in[7];
    const float* cw1    = (const float*)d_in[8];
    const float* cb1    = (const float*)d_in[9];
    const float* pxw1   = (const float*)d_in[10];
    const float* pyw1   = (const float*)d_in[11];
    const float* qkvw1  = (const float*)d_in[12];
    const float* projw1 = (const float*)d_in[13];
    const float* projb1 = (const float*)d_in[14];
    const float* outw   = (const float*)d_in[15];
    const float* outb   = (const float*)d_in[16];
    float* out = (float*)d_out;

    const int attn_smem = 4 * 64 * 68 * sizeof(float);  // 69632 B
    cudaFuncSetAttribute(win_attn, cudaFuncAttributeMaxDynamicSharedMemorySize,
                         attn_smem);

    repack_w1<<<72, 256>>>(cw1, pxw1, pyw1);
    layer0_gates<<<1024, 256>>>(x, cw0, cb0, pxw0, pyw0);          // -> buf0
    win_attn<<<4096, 256, attn_smem>>>(qkvw0, projw0, projb0);     // buf0 -> buf1
    layer1_gates<<<2048, 256>>>(cb1);                              // buf1 -> buf0
    win_attn<<<4096, 256, attn_smem>>>(qkvw1, projw1, projb1);     // buf0 -> buf1
    out_conv<<<1024, 256>>>(outw, outb, out);                      // buf1 -> d_out
}

// round 3
// speedup vs baseline: 1.3210x; 1.1754x over previous
#include <cuda_runtime.h>
#include <math.h>

#define BATCH 16
#define HDIM 128
#define WDIM 128
#define HID 64

typedef unsigned long long u64;

// ping-pong activation buffers (NHWC), 64MB each
__device__ __align__(16) float g_buf0[BATCH * HDIM * WDIM * HID];
__device__ __align__(16) float g_buf1[BATCH * HDIM * WDIM * HID];
// repacked layer-1 weights: [cp(32)][cin(64)*9+tap][12] (5 gates x 2 ch + pad)
__device__ __align__(16) float g_w1p[32 * 576 * 12];

__device__ __forceinline__ float sigm(float v) { return 1.0f / (1.0f + expf(-v)); }

__device__ __forceinline__ void fma2(u64& d, u64 a, u64 b) {
    asm("fma.rn.f32x2 %0, %1, %2, %0;" : "+l"(d) : "l"(a), "l"(b));
}
__device__ __forceinline__ u64 pack2(float v) {
    u64 r;
    asm("mov.b64 %0, {%1, %1};" : "=l"(r) : "f"(v));
    return r;
}
__device__ __forceinline__ void unpack2(u64 p, float& lo, float& hi) {
    asm("mov.b64 {%0, %1}, %2;" : "=f"(lo), "=f"(hi) : "l"(p));
}

// ---------------------------------------------------------------------------
// Repack layer-1 weights: gates {ci, co, cg, px, py} for channel pair cp.
// conv_w1: [256][128][3][3] (only first 64 in-ch used since h=0)
// k = cin*9 + tap (cin-major). 12-float rows -> ulonglong2 loads give packed
// (gate g, gate g+1) f32x2 operands directly.
// ---------------------------------------------------------------------------
__global__ void repack_w1(const float* __restrict__ cw,
                          const float* __restrict__ pxw,
                          const float* __restrict__ pyw) {
    int idx = blockIdx.x * 256 + threadIdx.x;   // cp*576 + k
    if (idx >= 32 * 576) return;
    int cp = idx / 576, k = idx % 576;
    int cin = k / 9, tap = k % 9;
    float* dst = g_w1p + idx * 12;
#pragma unroll
    for (int j = 0; j < 2; j++) {
        int c = cp * 2 + j;
        dst[j * 5 + 0] = cw[((c) * 128 + cin) * 9 + tap];        // ci
        dst[j * 5 + 1] = cw[((128 + c) * 128 + cin) * 9 + tap];  // co
        dst[j * 5 + 2] = cw[((192 + c) * 128 + cin) * 9 + tap];  // cg
        dst[j * 5 + 3] = pxw[(c * 64 + cin) * 9 + tap];          // px
        dst[j * 5 + 4] = pyw[(c * 64 + cin) * 9 + tap];          // py
    }
    dst[10] = 0.0f; dst[11] = 0.0f;
}

// ---------------------------------------------------------------------------
// Layer 0 fused gates: CIN=1. Each thread = one pixel, loops 64 channels.
// ---------------------------------------------------------------------------
__global__ __launch_bounds__(256) void layer0_gates(
    const float* __restrict__ x, const float* __restrict__ cw,
    const float* __restrict__ cb, const float* __restrict__ pxw,
    const float* __restrict__ pyw) {
    __shared__ float s_w[5][64][9];
    __shared__ float s_b[3][64];
    int tid = threadIdx.x;
    for (int i = tid; i < 576; i += 256) {
        int c = i / 9, j = i % 9;
        s_w[0][c][j] = cw[c * 585 + j];
        s_w[1][c][j] = cw[(128 + c) * 585 + j];
        s_w[2][c][j] = cw[(192 + c) * 585 + j];
        s_w[3][c][j] = pxw[i];
        s_w[4][c][j] = pyw[i];
    }
    if (tid < 64) {
        s_b[0][tid] = cb[tid];
        s_b[1][tid] = cb[128 + tid];
        s_b[2][tid] = cb[192 + tid];
    }
    __syncthreads();

    int p = blockIdx.x * 256 + tid;                 // pixel id [0, 262144)
    int b = p >> 14, y = (p >> 7) & 127, xc = p & 127;
    float pv[9];
#pragma unroll
    for (int ky = 0; ky < 3; ky++)
#pragma unroll
        for (int kx = 0; kx < 3; kx++) {
            int gy = y + ky - 1, gx = xc + kx - 1;
            pv[ky * 3 + kx] = (gy >= 0 && gy < 128 && gx >= 0 && gx < 128)
                                  ? x[(b << 14) + gy * 128 + gx] : 0.0f;
        }
    float* outp = g_buf0 + (p << 6);
    for (int c = 0; c < 64; c++) {
        float aci = 0.f, aco = 0.f, acg = 0.f, apx = 0.f, apy = 0.f;
#pragma unroll
        for (int j = 0; j < 9; j++) {
            float a = pv[j];
            aci += a * s_w[0][c][j];
            aco += a * s_w[1][c][j];
            acg += a * s_w[2][c][j];
            apx += a * s_w[3][c][j];
            apy += a * s_w[4][c][j];
        }
        float ig = sigm(aci + apx + s_b[0][c]);
        float og = sigm(aco + apy + s_b[1][c]);
        float gg = tanhf(acg + apy + s_b[2][c]);
        outp[c] = og * tanhf(ig * gg);
    }
}

// ---------------------------------------------------------------------------
// Window attention: one block per 8x8 window (4096 blocks).
// ---------------------------------------------------------------------------
__global__ __launch_bounds__(256) void win_attn(
    const float* __restrict__ qkvw, const float* __restrict__ projw,
    const float* __restrict__ projb) {
    extern __shared__ float sm[];
    float* s_in = sm;                 // [64][68]  x, later o
    float* s_q = sm + 64 * 68;
    float* s_k = s_q + 64 * 68;
    float* s_v = s_k + 64 * 68;
    int tid = threadIdx.x;
    int wid = blockIdx.x;
    int b = wid >> 8, wy = (wid >> 4) & 15, wx = wid & 15;
    int base = ((b * 128 + wy * 8) * 128 + wx * 8) * 64;

    for (int i = tid; i < 4096; i += 256) {
        int t = i >> 6, c = i & 63;
        int ty = t >> 3, tx = t & 7;
        s_in[t * 68 + c] = g_buf0[base + (ty * 128 + tx) * 64 + c];
    }
    __syncthreads();

    // ---- QKV: 16 token-groups x 16 row-groups, thread tile 4 tokens x 12 rows
    {
        int tt = tid & 15, tr = tid >> 4;
        int t0 = tt * 4, r0 = tr * 12;
        float acc[12][4];
#pragma unroll
        for (int j = 0; j < 12; j++)
#pragma unroll
            for (int i2 = 0; i2 < 4; i2++) acc[j][i2] = 0.0f;
        for (int c = 0; c < 64; c += 4) {
            float4 a[4];
#pragma unroll
            for (int i2 = 0; i2 < 4; i2++)
                a[i2] = *(const float4*)(s_in + (t0 + i2) * 68 + c);
#pragma unroll
            for (int j = 0; j < 12; j++) {
                float4 w = __ldg((const float4*)(qkvw + (r0 + j) * 64 + c));
#pragma unroll
                for (int i2 = 0; i2 < 4; i2++)
                    acc[j][i2] += w.x * a[i2].x + w.y * a[i2].y +
                                  w.z * a[i2].z + w.w * a[i2].w;
            }
        }
#pragma unroll
        for (int j = 0; j < 12; j++) {
            int r = r0 + j;
            float* dst; float scl = 1.0f; int rr;
            if (r < 64)       { dst = s_q; rr = r;       scl = 0.25f; } // HD^-0.5
            else if (r < 128) { dst = s_k; rr = r - 64; }
            else              { dst = s_v; rr = r - 128; }
#pragma unroll
            for (int i2 = 0; i2 < 4; i2++)
                dst[(t0 + i2) * 68 + rr] = acc[j][i2] * scl;
        }
    }
    __syncthreads();

    // ---- attention: thread = (head, query); scores fully in registers
    {
        int h = tid >> 6, qi = tid & 63;
        int d0 = h * 16;
        float qv[16];
#pragma unroll
        for (int d4 = 0; d4 < 4; d4++) {
            float4 q4 = *(const float4*)(s_q + qi * 68 + d0 + d4 * 4);
            qv[d4 * 4 + 0] = q4.x; qv[d4 * 4 + 1] = q4.y;
            qv[d4 * 4 + 2] = q4.z; qv[d4 * 4 + 3] = q4.w;
        }
        float scv[64];
#pragma unroll
        for (int kj = 0; kj < 64; kj++) {
            const float* kp = s_k + kj * 68 + d0;
            float s = 0.0f;
#pragma unroll
            for (int d4 = 0; d4 < 4; d4++) {
                float4 k4 = *(const float4*)(kp + d4 * 4);
                s += qv[d4 * 4 + 0] * k4.x + qv[d4 * 4 + 1] * k4.y +
                     qv[d4 * 4 + 2] * k4.z + qv[d4 * 4 + 3] * k4.w;
            }
            scv[kj] = s;
        }
        float m = scv[0];
#pragma unroll
        for (int kj = 1; kj < 64; kj++) m = fmaxf(m, scv[kj]);
        float sum = 0.0f;
#pragma unroll
        for (int kj = 0; kj < 64; kj++) { scv[kj] = __expf(scv[kj] - m); sum += scv[kj]; }
        float ov[16];
#pragma unroll
        for (int d = 0; d < 16; d++) ov[d] = 0.0f;
#pragma unroll
        for (int kj = 0; kj < 64; kj++) {
            const float* vp = s_v + kj * 68 + d0;
            float pp = scv[kj];
#pragma unroll
            for (int d4 = 0; d4 < 4; d4++) {
                float4 v4 = *(const float4*)(vp + d4 * 4);
                ov[d4 * 4 + 0] += pp * v4.x; ov[d4 * 4 + 1] += pp * v4.y;
                ov[d4 * 4 + 2] += pp * v4.z; ov[d4 * 4 + 3] += pp * v4.w;
            }
        }
        float inv = 1.0f / sum;
#pragma unroll
        for (int d = 0; d < 16; d++) s_in[qi * 68 + d0 + d] = ov[d] * inv;
    }
    __syncthreads();

    // ---- proj: out = o @ proj_w.T + b; thread tile 4 tokens x 4 channels
    {
        int tt = tid & 15, tc = tid >> 4;
        int t0 = tt * 4, c0 = tc * 4;
        float acc[4][4];
#pragma unroll
        for (int j = 0; j < 4; j++)
#pragma unroll
            for (int i2 = 0; i2 < 4; i2++) acc[j][i2] = 0.0f;
        for (int k = 0; k < 64; k += 4) {
            float4 a[4];
#pragma unroll
            for (int i2 = 0; i2 < 4; i2++)
                a[i2] = *(const float4*)(s_in + (t0 + i2) * 68 + k);
#pragma unroll
            for (int j = 0; j < 4; j++) {
                float4 w = __ldg((const float4*)(projw + (c0 + j) * 64 + k));
#pragma unroll
                for (int i2 = 0; i2 < 4; i2++)
                    acc[j][i2] += w.x * a[i2].x + w.y * a[i2].y +
                                  w.z * a[i2].z + w.w * a[i2].w;
            }
        }
#pragma unroll
        for (int i2 = 0; i2 < 4; i2++) {
            int t = t0 + i2;
            int ty = t >> 3, tx = t & 7;
            int oidx = base + (ty * 128 + tx) * 64 + c0;
#pragma unroll
            for (int j = 0; j < 4; j++)
                g_buf1[oidx + j] = acc[j][i2] + __ldg(projb + c0 + j);
        }
    }
}

// ---------------------------------------------------------------------------
// Layer 1 fused gates (97 GFLOP conv), v3: FFMA2 (fma.rn.f32x2).
// Block tile: 8 rows x 16 cols. Thread: 8-row column x channel pair,
// 10 gate outputs packed as 5 f32x2 accumulators (40 u64 regs).
// Weights arrive pre-paired via ulonglong2 LDG.128; only the activation
// broadcast needs a mov.b64 pack (alu pipe, off the fma pipe).
// __launch_bounds__(256,2) caps regs at 128 -> 2 CTAs/SM (16 warps).
// ---------------------------------------------------------------------------
#define C_STRIDE 186
__global__ __launch_bounds__(256, 2) void layer1_gates(const float* __restrict__ cb) {
    __shared__ float s_in[64 * C_STRIDE];   // 47616 B
    int tile = blockIdx.x;            // 2048 = 16b x 16 tile-rows x 8 tile-cols
    int b = tile >> 7;
    int trow = (tile >> 3) & 15;
    int tcol = tile & 7;
    int y0 = trow * 8, x0 = tcol * 16;
    int tid = threadIdx.x;

    // halo fill: [c][xx 0..17][yy 0..9]; gy = y0+yy-1, gx = x0+xx-1
    for (int i = tid; i < 64 * 180; i += 256) {
        int c = i & 63, pos = i >> 6;
        int xx = pos / 10, yy = pos % 10;
        int gy = y0 + yy - 1, gx = x0 + xx - 1;
        float v = 0.0f;
        if (gy >= 0 && gy < 128 && gx >= 0 && gx < 128)
            v = g_buf1[(((b << 7) + gy) * 128 + gx) * 64 + c];
        s_in[c * C_STRIDE + xx * 10 + yy] = v;
    }
    __syncthreads();

    int px = tid & 15;        // pixel column 0..15
    int cg = tid >> 4;        // channel-pair slot 0..15

#pragma unroll 1
    for (int chunk = 0; chunk < 2; chunk++) {
        int cp = chunk * 16 + cg;                       // channel pair id
        const ulonglong2* wrow = (const ulonglong2*)(g_w1p + cp * 576 * 12);
        u64 acc[8][5];
        u64 zz = pack2(0.0f);
#pragma unroll
        for (int i = 0; i < 8; i++)
#pragma unroll
            for (int g = 0; g < 5; g++) acc[i][g] = zz;

#pragma unroll 1
        for (int cin = 0; cin < 64; cin++) {
            const float* sc = s_in + cin * C_STRIDE;
#pragma unroll
            for (int kx = 0; kx < 3; kx++) {
                u64 ap[10];
                const float* col = sc + (px + kx) * 10;
#pragma unroll
                for (int r = 0; r < 10; r++) ap[r] = pack2(col[r]);
#pragma unroll
                for (int ky = 0; ky < 3; ky++) {
                    const ulonglong2* wp = wrow + (cin * 9 + ky * 3 + kx) * 3;
                    ulonglong2 wA = __ldg(wp), wB = __ldg(wp + 1), wC = __ldg(wp + 2);
                    u64 wv[5] = {wA.x, wA.y, wB.x, wB.y, wC.x};
#pragma unroll
                    for (int i = 0; i < 8; i++) {
                        u64 a2 = ap[i + ky];
#pragma unroll
                        for (int g = 0; g < 5; g++) fma2(acc[i][g], a2, wv[g]);
                    }
                }
            }
        }
        // fused gate epilogue
#pragma unroll
        for (int i = 0; i < 8; i++) {
            float v[10];
#pragma unroll
            for (int g = 0; g < 5; g++) unpack2(acc[i][g], v[2 * g], v[2 * g + 1]);
#pragma unroll
            for (int j = 0; j < 2; j++) {
                int c = cp * 2 + j;
                float bci = __ldg(cb + c), bco = __ldg(cb + 128 + c),
                      bcg = __ldg(cb + 192 + c);
                float ci = v[j * 5 + 0], co = v[j * 5 + 1];
                float cgv = v[j * 5 + 2], pxv = v[j * 5 + 3];
                float pyv = v[j * 5 + 4];
                float ig = sigm(ci + pxv + bci);
                float og = sigm(co + pyv + bco);
                float gg = tanhf(cgv + pyv + bcg);
                int gy = y0 + i, gx = x0 + px;
                g_buf0[(((b << 7) + gy) * 128 + gx) * 64 + c] = og * tanhf(ig * gg);
            }
        }
    }
}

// ---------------------------------------------------------------------------
// Output 1x1 conv: out[p] = dot64(h1[p], out_w) + out_b
// ---------------------------------------------------------------------------
__global__ __launch_bounds__(256) void out_conv(const float* __restrict__ ow,
                                                const float* __restrict__ ob,
                                                float* __restrict__ out) {
    int p = blockIdx.x * 256 + threadIdx.x;
    const float4* hv = (const float4*)(g_buf1 + (p << 6));
    float acc = 0.0f;
#pragma unroll
    for (int k = 0; k < 16; k++) {
        float4 a = hv[k];
        float4 w = __ldg(((const float4*)ow) + k);
        acc += a.x * w.x + a.y * w.y + a.z * w.z + a.w * w.w;
    }
    out[p] = acc + __ldg(ob);
}

// ---------------------------------------------------------------------------
extern "C" void kernel_launch(void* const* d_in, const int* in_sizes, int n_in,
                              void* d_out, int out_size) {
    const float* x      = (const float*)d_in[0];
    const float* cw0    = (const float*)d_in[1];
    const float* cb0    = (const float*)d_in[2];
    const float* pxw0   = (const float*)d_in[3];
    const float* pyw0   = (const float*)d_in[4];
    const float* qkvw0  = (const float*)d_in[5];
    const float* projw0 = (const float*)d_in[6];
    const float* projb0 = (const float*)d_in[7];
    const float* cw1    = (const float*)d_in[8];
    const float* cb1    = (const float*)d_in[9];
    const float* pxw1   = (const float*)d_in[10];
    const float* pyw1   = (const float*)d_in[11];
    const float* qkvw1  = (const float*)d_in[12];
    const float* projw1 = (const float*)d_in[13];
    const float* projb1 = (const float*)d_in[14];
    const float* outw   = (const float*)d_in[15];
    const float* outb   = (const float*)d_in[16];
    float* out = (float*)d_out;

    const int attn_smem = 4 * 64 * 68 * sizeof(float);  // 69632 B
    cudaFuncSetAttribute(win_attn, cudaFuncAttributeMaxDynamicSharedMemorySize,
                         attn_smem);

    repack_w1<<<72, 256>>>(cw1, pxw1, pyw1);
    layer0_gates<<<1024, 256>>>(x, cw0, cb0, pxw0, pyw0);          // -> buf0
    win_attn<<<4096, 256, attn_smem>>>(qkvw0, projw0, projb0);     // buf0 -> buf1
    layer1_gates<<<2048, 256>>>(cb1);                              // buf1 -> buf0
    win_attn<<<4096, 256, attn_smem>>>(qkvw1, projw1, projb1);     // buf0 -> buf1
    out_conv<<<1024, 256>>>(outw, outb, out);                      // buf1 -> d_out
}

// round 5
// speedup vs baseline: 2.3112x; 1.7497x over previous
#include <cuda_runtime.h>
#include <cuda_fp16.h>
#include <math.h>
#include <stdint.h>

#define BATCH 16
#define HDIM 128
#define WDIM 128
#define HID 64

typedef uint32_t u32;

// ping-pong activation buffers (NHWC), fp32
__device__ __align__(16) float g_buf0[BATCH * HDIM * WDIM * HID];
__device__ __align__(16) float g_buf1[BATCH * HDIM * WDIM * HID];
// padded f16 activations for layer-1 conv: [16][130][130][64]
__device__ __align__(16) __half g_h16[BATCH * 130 * 130 * HID];
// f16 layer-1 weights: [tap 9][gate*64+oc 320][cin 64]
__device__ __align__(16) __half g_w1h[9 * 320 * 64];

__device__ __forceinline__ float sigm(float v) { return 1.0f / (1.0f + expf(-v)); }

// ===================== sm_80+ tensor helpers (no 'a' target) ================
__device__ __forceinline__ u32 smem_u32(const void* p) {
    u32 a;
    asm("{ .reg .u64 t; cvta.to.shared.u64 t, %1; cvt.u32.u64 %0, t; }"
        : "=r"(a) : "l"(p));
    return a;
}
__device__ __forceinline__ void cp16(u32 dst, const void* src) {
    asm volatile("cp.async.cg.shared.global [%0], [%1], 16;" :: "r"(dst), "l"(src));
}
#define CPASYNC_COMMIT() asm volatile("cp.async.commit_group;" ::: "memory")
#define CPASYNC_WAIT0()  asm volatile("cp.async.wait_group 0;" ::: "memory")

__device__ __forceinline__ void ldsm4(u32* r, u32 a) {
    asm volatile("ldmatrix.sync.aligned.m8n8.x4.shared.b16 {%0,%1,%2,%3}, [%4];"
                 : "=r"(r[0]), "=r"(r[1]), "=r"(r[2]), "=r"(r[3]) : "r"(a));
}
__device__ __forceinline__ void mma16816(float* c, const u32* a, u32 b0, u32 b1) {
    asm volatile(
        "mma.sync.aligned.m16n8k16.row.col.f32.f16.f16.f32 "
        "{%0,%1,%2,%3}, {%4,%5,%6,%7}, {%8,%9}, {%0,%1,%2,%3};"
        : "+f"(c[0]), "+f"(c[1]), "+f"(c[2]), "+f"(c[3])
        : "r"(a[0]), "r"(a[1]), "r"(a[2]), "r"(a[3]), "r"(b0), "r"(b1));
}
// SW128 swizzle on byte offset within a 128B-row tile
#define SWZ(o) ((o) ^ (((o) >> 3) & 0x70))

// ---------------------------------------------------------------------------
// Repack layer-1 weights to f16: g_w1h[tap][g*64+n][cin]
// gates {ci, co, cg, px, py}; conv_w1: [256][128][3][3], h=0 -> cin<64
// ---------------------------------------------------------------------------
__global__ void repack_w1h(const float* __restrict__ cw,
                           const float* __restrict__ pxw,
                           const float* __restrict__ pyw) {
    int idx = blockIdx.x * 256 + threadIdx.x;   // 9*320*64 = 184320
    if (idx >= 9 * 320 * 64) return;
    int tap = idx / (320 * 64);
    int rem = idx % (320 * 64);
    int r = rem / 64, cin = rem % 64;
    int g = r >> 6, n = r & 63;
    float v;
    if (g == 0)      v = cw[(n * 128 + cin) * 9 + tap];
    else if (g == 1) v = cw[((128 + n) * 128 + cin) * 9 + tap];
    else if (g == 2) v = cw[((192 + n) * 128 + cin) * 9 + tap];
    else if (g == 3) v = pxw[(n * 64 + cin) * 9 + tap];
    else             v = pyw[(n * 64 + cin) * 9 + tap];
    g_w1h[idx] = __float2half_rn(v);
}

// zero the 1-pixel border of the padded f16 buffer
__global__ void zero_h16_borders() {
    int p = blockIdx.x * 256 + threadIdx.x;     // 16*130*130 = 270400 pixels
    if (p >= BATCH * 130 * 130) return;
    int bp = p % (130 * 130);
    int yy = bp / 130, xx = bp % 130;
    if (yy == 0 || yy == 129 || xx == 0 || xx == 129) {
        uint4* d = (uint4*)(g_h16 + (size_t)p * 64);
        uint4 z = {0, 0, 0, 0};
#pragma unroll
        for (int i = 0; i < 8; i++) d[i] = z;
    }
}

// ---------------------------------------------------------------------------
// Layer 0 fused gates: CIN=1.
// ---------------------------------------------------------------------------
__global__ __launch_bounds__(256) void layer0_gates(
    const float* __restrict__ x, const float* __restrict__ cw,
    const float* __restrict__ cb, const float* __restrict__ pxw,
    const float* __restrict__ pyw) {
    __shared__ float s_w[5][64][9];
    __shared__ float s_b[3][64];
    int tid = threadIdx.x;
    for (int i = tid; i < 576; i += 256) {
        int c = i / 9, j = i % 9;
        s_w[0][c][j] = cw[c * 585 + j];
        s_w[1][c][j] = cw[(128 + c) * 585 + j];
        s_w[2][c][j] = cw[(192 + c) * 585 + j];
        s_w[3][c][j] = pxw[i];
        s_w[4][c][j] = pyw[i];
    }
    if (tid < 64) {
        s_b[0][tid] = cb[tid];
        s_b[1][tid] = cb[128 + tid];
        s_b[2][tid] = cb[192 + tid];
    }
    __syncthreads();

    int p = blockIdx.x * 256 + tid;
    int b = p >> 14, y = (p >> 7) & 127, xc = p & 127;
    float pv[9];
#pragma unroll
    for (int ky = 0; ky < 3; ky++)
#pragma unroll
        for (int kx = 0; kx < 3; kx++) {
            int gy = y + ky - 1, gx = xc + kx - 1;
            pv[ky * 3 + kx] = (gy >= 0 && gy < 128 && gx >= 0 && gx < 128)
                                  ? x[(b << 14) + gy * 128 + gx] : 0.0f;
        }
    float* outp = g_buf0 + ((size_t)p << 6);
    for (int c = 0; c < 64; c++) {
        float aci = 0.f, aco = 0.f, acg = 0.f, apx = 0.f, apy = 0.f;
#pragma unroll
        for (int j = 0; j < 9; j++) {
            float a = pv[j];
            aci += a * s_w[0][c][j];
            aco += a * s_w[1][c][j];
            acg += a * s_w[2][c][j];
            apx += a * s_w[3][c][j];
            apy += a * s_w[4][c][j];
        }
        float ig = sigm(aci + apx + s_b[0][c]);
        float og = sigm(aco + apy + s_b[1][c]);
        float gg = tanhf(acg + apy + s_b[2][c]);
        outp[c] = og * tanhf(ig * gg);
    }
}

// ---------------------------------------------------------------------------
// Window attention: one block per 8x8 window (4096 blocks). Reads g_buf0.
// to_h16=1: write padded f16 g_h16; to_h16=0: write fp32 g_buf1.
// ---------------------------------------------------------------------------
__global__ __launch_bounds__(256) void win_attn(
    const float* __restrict__ qkvw, const float* __restrict__ projw,
    const float* __restrict__ projb, int to_h16) {
    extern __shared__ float sm[];
    float* s_in = sm;                 // [64][68]
    float* s_q = sm + 64 * 68;
    float* s_k = s_q + 64 * 68;
    float* s_v = s_k + 64 * 68;
    int tid = threadIdx.x;
    int wid = blockIdx.x;
    int b = wid >> 8, wy = (wid >> 4) & 15, wx = wid & 15;
    int base = ((b * 128 + wy * 8) * 128 + wx * 8) * 64;

    for (int i = tid; i < 4096; i += 256) {
        int t = i >> 6, c = i & 63;
        int ty = t >> 3, tx = t & 7;
        s_in[t * 68 + c] = g_buf0[base + (ty * 128 + tx) * 64 + c];
    }
    __syncthreads();

    // QKV
    {
        int tt = tid & 15, tr = tid >> 4;
        int t0 = tt * 4, r0 = tr * 12;
        float acc[12][4];
#pragma unroll
        for (int j = 0; j < 12; j++)
#pragma unroll
            for (int i2 = 0; i2 < 4; i2++) acc[j][i2] = 0.0f;
        for (int c = 0; c < 64; c += 4) {
            float4 a[4];
#pragma unroll
            for (int i2 = 0; i2 < 4; i2++)
                a[i2] = *(const float4*)(s_in + (t0 + i2) * 68 + c);
#pragma unroll
            for (int j = 0; j < 12; j++) {
                float4 w = __ldg((const float4*)(qkvw + (r0 + j) * 64 + c));
#pragma unroll
                for (int i2 = 0; i2 < 4; i2++)
                    acc[j][i2] += w.x * a[i2].x + w.y * a[i2].y +
                                  w.z * a[i2].z + w.w * a[i2].w;
            }
        }
#pragma unroll
        for (int j = 0; j < 12; j++) {
            int r = r0 + j;
            float* dst; float scl = 1.0f; int rr;
            if (r < 64)       { dst = s_q; rr = r;       scl = 0.25f; }
            else if (r < 128) { dst = s_k; rr = r - 64; }
            else              { dst = s_v; rr = r - 128; }
#pragma unroll
            for (int i2 = 0; i2 < 4; i2++)
                dst[(t0 + i2) * 68 + rr] = acc[j][i2] * scl;
        }
    }
    __syncthreads();

    // attention
    {
        int h = tid >> 6, qi = tid & 63;
        int d0 = h * 16;
        float qv[16];
#pragma unroll
        for (int d4 = 0; d4 < 4; d4++) {
            float4 q4 = *(const float4*)(s_q + qi * 68 + d0 + d4 * 4);
            qv[d4 * 4 + 0] = q4.x; qv[d4 * 4 + 1] = q4.y;
            qv[d4 * 4 + 2] = q4.z; qv[d4 * 4 + 3] = q4.w;
        }
        float scv[64];
#pragma unroll
        for (int kj = 0; kj < 64; kj++) {
            const float* kp = s_k + kj * 68 + d0;
            float s = 0.0f;
#pragma unroll
            for (int d4 = 0; d4 < 4; d4++) {
                float4 k4 = *(const float4*)(kp + d4 * 4);
                s += qv[d4 * 4 + 0] * k4.x + qv[d4 * 4 + 1] * k4.y +
                     qv[d4 * 4 + 2] * k4.z + qv[d4 * 4 + 3] * k4.w;
            }
            scv[kj] = s;
        }
        float m = scv[0];
#pragma unroll
        for (int kj = 1; kj < 64; kj++) m = fmaxf(m, scv[kj]);
        float sum = 0.0f;
#pragma unroll
        for (int kj = 0; kj < 64; kj++) { scv[kj] = __expf(scv[kj] - m); sum += scv[kj]; }
        float ov[16];
#pragma unroll
        for (int d = 0; d < 16; d++) ov[d] = 0.0f;
#pragma unroll
        for (int kj = 0; kj < 64; kj++) {
            const float* vp = s_v + kj * 68 + d0;
            float pp = scv[kj];
#pragma unroll
            for (int d4 = 0; d4 < 4; d4++) {
                float4 v4 = *(const float4*)(vp + d4 * 4);
                ov[d4 * 4 + 0] += pp * v4.x; ov[d4 * 4 + 1] += pp * v4.y;
                ov[d4 * 4 + 2] += pp * v4.z; ov[d4 * 4 + 3] += pp * v4.w;
            }
        }
        float inv = 1.0f / sum;
#pragma unroll
        for (int d = 0; d < 16; d++) s_in[qi * 68 + d0 + d] = ov[d] * inv;
    }
    __syncthreads();

    // proj
    {
        int tt = tid & 15, tc = tid >> 4;
        int t0 = tt * 4, c0 = tc * 4;
        float acc[4][4];
#pragma unroll
        for (int j = 0; j < 4; j++)
#pragma unroll
            for (int i2 = 0; i2 < 4; i2++) acc[j][i2] = 0.0f;
        for (int k = 0; k < 64; k += 4) {
            float4 a[4];
#pragma unroll
            for (int i2 = 0; i2 < 4; i2++)
                a[i2] = *(const float4*)(s_in + (t0 + i2) * 68 + k);
#pragma unroll
            for (int j = 0; j < 4; j++) {
                float4 w = __ldg((const float4*)(projw + (c0 + j) * 64 + k));
#pragma unroll
                for (int i2 = 0; i2 < 4; i2++)
                    acc[j][i2] += w.x * a[i2].x + w.y * a[i2].y +
                                  w.z * a[i2].z + w.w * a[i2].w;
            }
        }
        float bias[4];
#pragma unroll
        for (int j = 0; j < 4; j++) bias[j] = __ldg(projb + c0 + j);
#pragma unroll
        for (int i2 = 0; i2 < 4; i2++) {
            int t = t0 + i2;
            int ty = t >> 3, tx = t & 7;
            int gy = wy * 8 + ty, gx = wx * 8 + tx;
            if (to_h16) {
                __half* dst = g_h16 +
                    ((size_t)((b * 130 + gy + 1) * 130 + gx + 1)) * 64 + c0;
#pragma unroll
                for (int j = 0; j < 4; j++)
                    dst[j] = __float2half_rn(acc[j][i2] + bias[j]);
            } else {
                int oidx = base + (ty * 128 + tx) * 64 + c0;
#pragma unroll
                for (int j = 0; j < 4; j++)
                    g_buf1[oidx + j] = acc[j][i2] + bias[j];
            }
        }
    }
}

// ---------------------------------------------------------------------------
// Layer 1 conv on the tensor pipe via mma.sync (m16n8k16 f16 -> f32).
// CTA = one image row: M=128 px, N=320 (5 gates x 64 oc), K = 9 taps x 64.
// 16 warps: warp (wm, wn) = M rows wm*32..+31, oc cols wn*16..+15, ALL 5
// gates -> 10 n8-tiles, 80 accum regs, fused gate epilogue in registers.
// A: 3 padded input rows [3*130][64]f16, SW128-swizzled, staged once.
// B: per-tap [320][64]f16, double-buffered, cp.async prefetch under mma.
// ---------------------------------------------------------------------------
#define L1_A_OFF 0
#define L1_A_BYTES (390 * 128)
#define L1_B0 L1_A_BYTES
#define L1_B_BYTES (320 * 128)
#define L1_B1 (L1_B0 + L1_B_BYTES)
#define L1_SMEM_TOTAL (L1_B1 + L1_B_BYTES)   // 131840

__device__ __forceinline__ void l1_load_B(u32 sB, int tap, int tid) {
    if (tid < 320) {
        const __half* src = g_w1h + (size_t)(tap * 320 + tid) * 64;
        u32 row = tid * 128;
        u32 sw = (u32)((tid & 7) << 4);
#pragma unroll
        for (int i = 0; i < 8; i++)
            cp16(sB + ((row + i * 16) ^ sw), (const char*)src + i * 16);
    }
}

__global__ __launch_bounds__(512, 1) void layer1_tc(const float* __restrict__ cb) {
    extern __shared__ char smem[];
    u32 sb = smem_u32(smem);
    int tid = threadIdx.x, lane = tid & 31, warp = tid >> 5;
    int wm = warp & 3, wn = warp >> 2;          // wm: M group, wn: oc group
    int tile = blockIdx.x;                      // b*128 + y
    int b = tile >> 7, y = tile & 127;

    // stage A: 3 padded rows (y, y+1, y+2 in padded coords) x 130 cols x 128B
    if (tid < 390) {
        int rowIdx = tid / 130, col = tid % 130;
        const __half* src = g_h16 +
            ((size_t)((b * 130 + y + rowIdx) * 130 + col)) * 64;
        u32 row = (u32)tid * 128;
        u32 sw = (u32)((tid & 7) << 4);
#pragma unroll
        for (int i = 0; i < 8; i++)
            cp16(sb + L1_A_OFF + ((row + i * 16) ^ sw), (const char*)src + i * 16);
    }
    l1_load_B(sb + L1_B0, 0, tid);
    CPASYNC_COMMIT();
    CPASYNC_WAIT0();
    __syncthreads();

    float c[2][5][2][4];
#pragma unroll
    for (int mi = 0; mi < 2; mi++)
#pragma unroll
        for (int g5 = 0; g5 < 5; g5++)
#pragma unroll
            for (int nt = 0; nt < 2; nt++)
#pragma unroll
                for (int e = 0; e < 4; e++) c[mi][g5][nt][e] = 0.0f;

    // per-lane invariants
    int arow = wm * 32 + (lane & 7) + 8 * ((lane >> 3) & 1);  // pixel row in tile
    u32 aklane = (u32)(16 * (lane >> 4));                     // A k-byte select
    u32 bkl = (u32)(((lane >> 3) & 1) * 16);                  // B k-byte select
    int bnrow_base = wn * 16 + ((lane >> 4) & 1) * 8 + (lane & 7);
    u32 bswz = (u32)((lane & 7) << 4);

#pragma unroll 1
    for (int tap = 0; tap < 9; tap++) {
        u32 Bb = sb + ((tap & 1) ? L1_B1 : L1_B0);
        // prefetch next tap's B into the other buffer
        if (tap < 8) {
            l1_load_B(sb + ((tap & 1) ? L1_B0 : L1_B1), tap + 1, tid);
            CPASYNC_COMMIT();
        }
        int dy = tap / 3, dx = tap % 3;         // dy,dx in 0..2 (padded offsets)
        int br0 = dy * 130 + arow + dx;         // A buffer row (mi=0)
#pragma unroll
        for (int ks = 0; ks < 4; ks++) {
            u32 a[2][4];
#pragma unroll
            for (int mi = 0; mi < 2; mi++) {
                u32 br = (u32)(br0 + mi * 16);
                u32 off = br * 128 + (u32)(ks * 32) + aklane;
                ldsm4(a[mi], sb + L1_A_OFF + (off ^ ((br & 7) << 4)));
            }
#pragma unroll
            for (int g5 = 0; g5 < 5; g5++) {
                u32 bfr[4];
                u32 nrow = (u32)(g5 * 64 + bnrow_base);
                u32 off = nrow * 128 + (u32)(ks * 32) + bkl;
                ldsm4(bfr, Bb + (off ^ bswz));
#pragma unroll
                for (int mi = 0; mi < 2; mi++) {
                    mma16816(c[mi][g5][0], a[mi], bfr[0], bfr[1]);
                    mma16816(c[mi][g5][1], a[mi], bfr[2], bfr[3]);
                }
            }
        }
        if (tap < 8) { CPASYNC_WAIT0(); }
        __syncthreads();
    }

    // fused gate epilogue: thread owns 4 pixel-rows x 4 channels, all 5 gates
    int q = lane & 3, gr = lane >> 2;
    int ocB = wn * 16;
#pragma unroll
    for (int mi = 0; mi < 2; mi++) {
#pragma unroll
        for (int rh = 0; rh < 2; rh++) {
            int x = wm * 32 + mi * 16 + gr + rh * 8;
            float* orow = g_buf0 + ((size_t)((b * 128 + y) * 128 + x)) * 64;
#pragma unroll
            for (int nt = 0; nt < 2; nt++) {
#pragma unroll
                for (int e = 0; e < 2; e++) {
                    int oc = ocB + nt * 8 + q * 2 + e;
                    int ai = rh * 2 + e;
                    float ci = c[mi][0][nt][ai];
                    float co = c[mi][1][nt][ai];
                    float cg = c[mi][2][nt][ai];
                    float px = c[mi][3][nt][ai];
                    float py = c[mi][4][nt][ai];
                    float ig = sigm(ci + px + __ldg(cb + oc));
                    float og = sigm(co + py + __ldg(cb + 128 + oc));
                    float gg = tanhf(cg + py + __ldg(cb + 192 + oc));
                    orow[oc] = og * tanhf(ig * gg);
                }
            }
        }
    }
}

// ---------------------------------------------------------------------------
// Output 1x1 conv
// ---------------------------------------------------------------------------
__global__ __launch_bounds__(256) void out_conv(const float* __restrict__ ow,
                                                const float* __restrict__ ob,
                                                float* __restrict__ out) {
    int p = blockIdx.x * 256 + threadIdx.x;
    const float4* hv = (const float4*)(g_buf1 + ((size_t)p << 6));
    float acc = 0.0f;
#pragma unroll
    for (int k = 0; k < 16; k++) {
        float4 a = hv[k];
        float4 w = __ldg(((const float4*)ow) + k);
        acc += a.x * w.x + a.y * w.y + a.z * w.z + a.w * w.w;
    }
    out[p] = acc + __ldg(ob);
}

// ---------------------------------------------------------------------------
extern "C" void kernel_launch(void* const* d_in, const int* in_sizes, int n_in,
                              void* d_out, int out_size) {
    const float* x      = (const float*)d_in[0];
    const float* cw0    = (const float*)d_in[1];
    const float* cb0    = (const float*)d_in[2];
    const float* pxw0   = (const float*)d_in[3];
    const float* pyw0   = (const float*)d_in[4];
    const float* qkvw0  = (const float*)d_in[5];
    const float* projw0 = (const float*)d_in[6];
    const float* projb0 = (const float*)d_in[7];
    const float* cw1    = (const float*)d_in[8];
    const float* cb1    = (const float*)d_in[9];
    const float* pxw1   = (const float*)d_in[10];
    const float* pyw1   = (const float*)d_in[11];
    const float* qkvw1  = (const float*)d_in[12];
    const float* projw1 = (const float*)d_in[13];
    const float* projb1 = (const float*)d_in[14];
    const float* outw   = (const float*)d_in[15];
    const float* outb   = (const float*)d_in[16];
    float* out = (float*)d_out;

    const int attn_smem = 4 * 64 * 68 * sizeof(float);  // 69632 B
    cudaFuncSetAttribute(win_attn, cudaFuncAttributeMaxDynamicSharedMemorySize,
                         attn_smem);
    cudaFuncSetAttribute(layer1_tc, cudaFuncAttributeMaxDynamicSharedMemorySize,
                         L1_SMEM_TOTAL);

    repack_w1h<<<720, 256>>>(cw1, pxw1, pyw1);
    zero_h16_borders<<<1057, 256>>>();
    layer0_gates<<<1024, 256>>>(x, cw0, cb0, pxw0, pyw0);           // -> buf0
    win_attn<<<4096, 256, attn_smem>>>(qkvw0, projw0, projb0, 1);   // buf0 -> h16
    layer1_tc<<<2048, 512, L1_SMEM_TOTAL>>>(cb1);                   // h16 -> buf0
    win_attn<<<4096, 256, attn_smem>>>(qkvw1, projw1, projb1, 0);   // buf0 -> buf1
    out_conv<<<1024, 256>>>(outw, outb, out);                       // buf1 -> d_out
}

// round 8
// speedup vs baseline: 3.7697x; 1.6310x over previous
#include <cuda_runtime.h>
#include <cuda_fp16.h>
#include <math.h>
#include <stdint.h>

#define BATCH 16
#define HDIM 128
#define WDIM 128
#define HID 64

typedef uint32_t u32;
typedef uint16_t u16;

// ping-pong activation buffers (NHWC), fp32
__device__ __align__(16) float g_buf0[BATCH * HDIM * WDIM * HID];
__device__ __align__(16) float g_buf1[BATCH * HDIM * WDIM * HID];
// padded f16 activations for layer-1 conv: [16][130][130][64]
__device__ __align__(16) __half g_h16[BATCH * 130 * 130 * HID];
// f16 layer-1 weights: [tap 9][gate*64+oc 320][cin 64]
__device__ __align__(16) __half g_w1h[9 * 320 * 64];
// f16 attention weights hi/lo (Markidis split): per layer qkv [192][64], proj [64][64]
__device__ __align__(16) __half g_wqh[2][192 * 64];
__device__ __align__(16) __half g_wql[2][192 * 64];
__device__ __align__(16) __half g_wph[2][64 * 64];
__device__ __align__(16) __half g_wpl[2][64 * 64];

__device__ __forceinline__ float sigm(float v) { return 1.0f / (1.0f + expf(-v)); }

// ===================== sm_80+ tensor helpers (no 'a' target) ================
__device__ __forceinline__ u32 smem_u32(const void* p) {
    u32 a;
    asm("{ .reg .u64 t; cvta.to.shared.u64 t, %1; cvt.u32.u64 %0, t; }"
        : "=r"(a) : "l"(p));
    return a;
}
__device__ __forceinline__ void cp16(u32 dst, const void* src) {
    asm volatile("cp.async.cg.shared.global [%0], [%1], 16;" :: "r"(dst), "l"(src));
}
#define CPASYNC_COMMIT() asm volatile("cp.async.commit_group;" ::: "memory")
#define CPASYNC_WAIT0()  asm volatile("cp.async.wait_group 0;" ::: "memory")

__device__ __forceinline__ void ldsm4(u32* r, u32 a) {
    asm volatile("ldmatrix.sync.aligned.m8n8.x4.shared.b16 {%0,%1,%2,%3}, [%4];"
                 : "=r"(r[0]), "=r"(r[1]), "=r"(r[2]), "=r"(r[3]) : "r"(a));
}
__device__ __forceinline__ void mma16816(float* c, const u32* a, u32 b0, u32 b1) {
    asm volatile(
        "mma.sync.aligned.m16n8k16.row.col.f32.f16.f16.f32 "
        "{%0,%1,%2,%3}, {%4,%5,%6,%7}, {%8,%9}, {%0,%1,%2,%3};"
        : "+f"(c[0]), "+f"(c[1]), "+f"(c[2]), "+f"(c[3])
        : "r"(a[0]), "r"(a[1]), "r"(a[2]), "r"(a[3]), "r"(b0), "r"(b1));
}
__device__ __forceinline__ u32 pk2(float lo, float hi) {   // {lo | hi<<16}
    u32 r;
    asm("cvt.rn.f16x2.f32 %0, %1, %2;" : "=r"(r) : "f"(hi), "f"(lo));
    return r;
}
// f16 hi/lo split of a float pair
__device__ __forceinline__ void split2(float a, float b, u32& hi, u32& lo) {
    __half ha = __float2half_rn(a), hb = __float2half_rn(b);
    hi = ((u32)__half_as_ushort(hb) << 16) | (u32)__half_as_ushort(ha);
    lo = pk2(a - __half2float(ha), b - __half2float(hb));
}
__device__ __forceinline__ void sts32(u32 addr, u32 v) {
    asm volatile("st.shared.b32 [%0], %1;" :: "r"(addr), "r"(v));
}
__device__ __forceinline__ void sts16(u32 addr, float v) {
    u16 b = __half_as_ushort(__float2half_rn(v));
    asm volatile("st.shared.b16 [%0], %1;" :: "r"(addr), "h"(b) : "memory");
}

// ---------------------------------------------------------------------------
// Repack layer-1 weights to f16: g_w1h[tap][g*64+n][cin]
// ---------------------------------------------------------------------------
__global__ void repack_w1h(const float* __restrict__ cw,
                           const float* __restrict__ pxw,
                           const float* __restrict__ pyw) {
    int idx = blockIdx.x * 256 + threadIdx.x;   // 9*320*64 = 184320
    if (idx >= 9 * 320 * 64) return;
    int tap = idx / (320 * 64);
    int rem = idx % (320 * 64);
    int r = rem / 64, cin = rem % 64;
    int g = r >> 6, n = r & 63;
    float v;
    if (g == 0)      v = cw[(n * 128 + cin) * 9 + tap];
    else if (g == 1) v = cw[((128 + n) * 128 + cin) * 9 + tap];
    else if (g == 2) v = cw[((192 + n) * 128 + cin) * 9 + tap];
    else if (g == 3) v = pxw[(n * 64 + cin) * 9 + tap];
    else             v = pyw[(n * 64 + cin) * 9 + tap];
    g_w1h[idx] = __float2half_rn(v);
}

// repack attention weights (both layers) to f16 hi/lo
__global__ void repack_attn_h(const float* __restrict__ q0, const float* __restrict__ p0,
                              const float* __restrict__ q1, const float* __restrict__ p1) {
    int idx = blockIdx.x * 256 + threadIdx.x;
    if (idx < 192 * 64) {
        float v0 = q0[idx], v1 = q1[idx];
        __half h0 = __float2half_rn(v0), h1 = __float2half_rn(v1);
        g_wqh[0][idx] = h0; g_wql[0][idx] = __float2half_rn(v0 - __half2float(h0));
        g_wqh[1][idx] = h1; g_wql[1][idx] = __float2half_rn(v1 - __half2float(h1));
    }
    if (idx < 64 * 64) {
        float v0 = p0[idx], v1 = p1[idx];
        __half h0 = __float2half_rn(v0), h1 = __float2half_rn(v1);
        g_wph[0][idx] = h0; g_wpl[0][idx] = __float2half_rn(v0 - __half2float(h0));
        g_wph[1][idx] = h1; g_wpl[1][idx] = __float2half_rn(v1 - __half2float(h1));
    }
}

// zero the 1-pixel border of the padded f16 buffer
__global__ void zero_h16_borders() {
    int p = blockIdx.x * 256 + threadIdx.x;     // 16*130*130 = 270400 pixels
    if (p >= BATCH * 130 * 130) return;
    int bp = p % (130 * 130);
    int yy = bp / 130, xx = bp % 130;
    if (yy == 0 || yy == 129 || xx == 0 || xx == 129) {
        uint4* d = (uint4*)(g_h16 + (size_t)p * 64);
        uint4 z = {0, 0, 0, 0};
#pragma unroll
        for (int i = 0; i < 8; i++) d[i] = z;
    }
}

// ---------------------------------------------------------------------------
// Layer 0 fused gates: CIN=1.
// ---------------------------------------------------------------------------
__global__ __launch_bounds__(256) void layer0_gates(
    const float* __restrict__ x, const float* __restrict__ cw,
    const float* __restrict__ cb, const float* __restrict__ pxw,
    const float* __restrict__ pyw) {
    __shared__ float s_w[5][64][9];
    __shared__ float s_b[3][64];
    int tid = threadIdx.x;
    for (int i = tid; i < 576; i += 256) {
        int c = i / 9, j = i % 9;
        s_w[0][c][j] = cw[c * 585 + j];
        s_w[1][c][j] = cw[(128 + c) * 585 + j];
        s_w[2][c][j] = cw[(192 + c) * 585 + j];
        s_w[3][c][j] = pxw[i];
        s_w[4][c][j] = pyw[i];
    }
    if (tid < 64) {
        s_b[0][tid] = cb[tid];
        s_b[1][tid] = cb[128 + tid];
        s_b[2][tid] = cb[192 + tid];
    }
    __syncthreads();

    int p = blockIdx.x * 256 + tid;
    int b = p >> 14, y = (p >> 7) & 127, xc = p & 127;
    float pv[9];
#pragma unroll
    for (int ky = 0; ky < 3; ky++)
#pragma unroll
        for (int kx = 0; kx < 3; kx++) {
            int gy = y + ky - 1, gx = xc + kx - 1;
            pv[ky * 3 + kx] = (gy >= 0 && gy < 128 && gx >= 0 && gx < 128)
                                  ? x[(b << 14) + gy * 128 + gx] : 0.0f;
        }
    float* outp = g_buf0 + ((size_t)p << 6);
    for (int c = 0; c < 64; c++) {
        float aci = 0.f, aco = 0.f, acg = 0.f, apx = 0.f, apy = 0.f;
#pragma unroll
        for (int j = 0; j < 9; j++) {
            float a = pv[j];
            aci += a * s_w[0][c][j];
            aco += a * s_w[1][c][j];
            acg += a * s_w[2][c][j];
            apx += a * s_w[3][c][j];
            apy += a * s_w[4][c][j];
        }
        float ig = sigm(aci + apx + s_b[0][c]);
        float og = sigm(aco + apy + s_b[1][c]);
        float gg = tanhf(acg + apy + s_b[2][c]);
        outp[c] = og * tanhf(ig * gg);
    }
}

// ---------------------------------------------------------------------------
// Window attention on mma.sync with f16 hi/lo error compensation.
// Block = 1 window, 4 warps. All planes f16, 128B rows, SW128 swizzle.
// 3-term GEMMs: Ah*Bh + Al*Bh + Ah*Bl  (lo*lo dropped).
// smem: x hi/lo (reused for O), q, k, vt hi/lo; wq hi/lo; wp aliased onto vt.
// ---------------------------------------------------------------------------
#define AT_XH 0
#define AT_XL 8192
#define AT_QH 16384
#define AT_QL 24576
#define AT_KH 32768
#define AT_KL 40960
#define AT_VTH 49152
#define AT_VTL 57344
#define AT_WQH 65536
#define AT_WQL 90112
#define AT_SMEM 114688

__global__ __launch_bounds__(128) void win_attn_tc(
    int layer, const float* __restrict__ projb, int to_h16) {
    extern __shared__ char smem[];
    u32 sb = smem_u32(smem);
    int tid = threadIdx.x, lane = tid & 31, w = tid >> 5;
    int wid = blockIdx.x;
    int b = wid >> 8, wy = (wid >> 4) & 15, wx = wid & 15;
    int base = ((b * 128 + wy * 8) * 128 + wx * 8) * 64;

    // ---- stage qkv weights hi/lo + x (fp32 -> f16 hi/lo) ----
    for (int r = tid; r < 192; r += 128) {
        const __half* sh = g_wqh[layer] + r * 64;
        const __half* sl = g_wql[layer] + r * 64;
        u32 row = (u32)r * 128, sw = (u32)((r & 7) << 4);
#pragma unroll
        for (int i = 0; i < 8; i++) {
            cp16(sb + AT_WQH + ((row + i * 16) ^ sw), (const char*)sh + i * 16);
            cp16(sb + AT_WQL + ((row + i * 16) ^ sw), (const char*)sl + i * 16);
        }
    }
    CPASYNC_COMMIT();
    {
        int row = tid >> 1, half = tid & 1;           // token row, 32-col half
        int ty = row >> 3, tx = row & 7;
        const float* src = g_buf0 + base + (ty * 128 + tx) * 64 + half * 32;
        u32 sw = (u32)((row & 7) << 4);
#pragma unroll
        for (int j = 0; j < 8; j++) {
            float4 a = *(const float4*)(src + j * 4);
            u32 byte0 = (u32)(row * 128 + half * 64 + j * 8);
            u32 h01, l01, h23, l23;
            split2(a.x, a.y, h01, l01);
            split2(a.z, a.w, h23, l23);
            sts32(sb + AT_XH + (byte0 ^ sw), h01);
            sts32(sb + AT_XL + (byte0 ^ sw), l01);
            sts32(sb + AT_XH + ((byte0 + 4) ^ sw), h23);
            sts32(sb + AT_XL + ((byte0 + 4) ^ sw), l23);
        }
    }
    CPASYNC_WAIT0();
    __syncthreads();

    // lane-invariant ldsm address pieces
    int aRow = (lane & 7) + 8 * ((lane >> 3) & 1);
    u32 aKl = (u32)(16 * (lane >> 4));
    int bRow = ((lane >> 4) & 1) * 8 + (lane & 7);
    u32 bKl = (u32)(((lane >> 3) & 1) * 16);
    int g = lane >> 2, t = lane & 3;

    // ---- phase 1: QKV GEMM (3-term). warp w -> out cols [w*48, w*48+48) ----
    {
        float c[4][6][4];
#pragma unroll
        for (int mt = 0; mt < 4; mt++)
#pragma unroll
            for (int nt = 0; nt < 6; nt++)
#pragma unroll
                for (int e = 0; e < 4; e++) c[mt][nt][e] = 0.0f;

#pragma unroll
        for (int ks = 0; ks < 4; ks++) {
            u32 ah[4][4], al[4][4];
#pragma unroll
            for (int mt = 0; mt < 4; mt++) {
                u32 ar = (u32)(mt * 16 + aRow);
                u32 off = ar * 128 + (u32)(ks * 32) + aKl;
                u32 sw = ((ar & 7) << 4);
                ldsm4(ah[mt], sb + AT_XH + (off ^ sw));
                ldsm4(al[mt], sb + AT_XL + (off ^ sw));
            }
#pragma unroll
            for (int np = 0; np < 3; np++) {
                u32 bh[4], bl[4];
                u32 nr = (u32)(w * 48 + np * 16 + bRow);
                u32 off = nr * 128 + (u32)(ks * 32) + bKl;
                u32 sw = ((nr & 7) << 4);
                ldsm4(bh, sb + AT_WQH + (off ^ sw));
                ldsm4(bl, sb + AT_WQL + (off ^ sw));
#pragma unroll
                for (int mt = 0; mt < 4; mt++) {
                    mma16816(c[mt][np * 2], ah[mt], bh[0], bh[1]);
                    mma16816(c[mt][np * 2], al[mt], bh[0], bh[1]);
                    mma16816(c[mt][np * 2], ah[mt], bl[0], bl[1]);
                    mma16816(c[mt][np * 2 + 1], ah[mt], bh[2], bh[3]);
                    mma16816(c[mt][np * 2 + 1], al[mt], bh[2], bh[3]);
                    mma16816(c[mt][np * 2 + 1], ah[mt], bl[2], bl[3]);
                }
            }
        }
        // store Q (x0.25), K, V^T as f16 hi/lo
#pragma unroll
        for (int mt = 0; mt < 4; mt++) {
#pragma unroll
            for (int nt = 0; nt < 6; nt++) {
                int nc = w * 48 + nt * 8 + t * 2;
                int r0 = mt * 16 + g, r1 = r0 + 8;
                float v0 = c[mt][nt][0], v1 = c[mt][nt][1];
                float v2 = c[mt][nt][2], v3 = c[mt][nt][3];
                u32 sw0 = ((u32)(r0 & 7) << 4), sw1 = ((u32)(r1 & 7) << 4);
                if (nc < 64) {
                    u32 h01, l01, h23, l23;
                    split2(v0 * 0.25f, v1 * 0.25f, h01, l01);
                    split2(v2 * 0.25f, v3 * 0.25f, h23, l23);
                    u32 o0 = ((u32)(r0 * 128 + nc * 2)) ^ sw0;
                    u32 o1 = ((u32)(r1 * 128 + nc * 2)) ^ sw1;
                    sts32(sb + AT_QH + o0, h01); sts32(sb + AT_QL + o0, l01);
                    sts32(sb + AT_QH + o1, h23); sts32(sb + AT_QL + o1, l23);
                } else if (nc < 128) {
                    int kc = nc - 64;
                    u32 h01, l01, h23, l23;
                    split2(v0, v1, h01, l01);
                    split2(v2, v3, h23, l23);
                    u32 o0 = ((u32)(r0 * 128 + kc * 2)) ^ sw0;
                    u32 o1 = ((u32)(r1 * 128 + kc * 2)) ^ sw1;
                    sts32(sb + AT_KH + o0, h01); sts32(sb + AT_KL + o0, l01);
                    sts32(sb + AT_KH + o1, h23); sts32(sb + AT_KL + o1, l23);
                } else {
                    int d0 = nc - 128, d1 = d0 + 1;
                    u32 s0 = (u32)((d0 & 7) << 4), s1 = (u32)((d1 & 7) << 4);
                    float vv[4] = {v0, v1, v2, v3};
                    int dd[4] = {d0, d1, d0, d1};
                    int rr[4] = {r0, r0, r1, r1};
                    u32 ss[4] = {s0, s1, s0, s1};
#pragma unroll
                    for (int e = 0; e < 4; e++) {
                        __half h = __float2half_rn(vv[e]);
                        float rl = vv[e] - __half2float(h);
                        u32 off = ((u32)(dd[e] * 128 + rr[e] * 2)) ^ ss[e];
                        sts16(sb + AT_VTH + off, vv[e]);
                        sts16(sb + AT_VTL + off, rl);
                    }
                }
            }
        }
    }
    __syncthreads();

    // ---- phase 2: attention, warp = head ----
    {
        int h = w;
        u32 kbh[4][4], kbl[4][4], vbh[4][4], vbl[4][4];
#pragma unroll
        for (int np = 0; np < 4; np++) {
            u32 nr = (u32)(np * 16 + bRow);
            u32 off = nr * 128 + (u32)(h * 32) + bKl;
            u32 sw = ((nr & 7) << 4);
            ldsm4(kbh[np], sb + AT_KH + (off ^ sw));
            ldsm4(kbl[np], sb + AT_KL + (off ^ sw));
        }
#pragma unroll
        for (int ks = 0; ks < 4; ks++) {
            u32 nr = (u32)(h * 16 + bRow);
            u32 off = nr * 128 + (u32)(ks * 32) + bKl;
            u32 sw = ((nr & 7) << 4);
            ldsm4(vbh[ks], sb + AT_VTH + (off ^ sw));
            ldsm4(vbl[ks], sb + AT_VTL + (off ^ sw));
        }
        __syncthreads();   // all warps hold K/V fragments; vt planes now free
        // stage proj weights into the vt planes (overlap with compute)
        {
            int r = tid & 63;
            const __half* src = (tid < 64) ? (g_wph[layer] + r * 64)
                                           : (g_wpl[layer] + r * 64);
            u32 dstb = (tid < 64) ? (sb + AT_VTH) : (sb + AT_VTL);
            u32 row = (u32)r * 128, sw = (u32)((r & 7) << 4);
#pragma unroll
            for (int i = 0; i < 8; i++)
                cp16(dstb + ((row + i * 16) ^ sw), (const char*)src + i * 16);
            CPASYNC_COMMIT();
        }

#pragma unroll
        for (int mt = 0; mt < 4; mt++) {
            u32 aqh[4], aql[4];
            u32 ar = (u32)(mt * 16 + aRow);
            u32 off = ar * 128 + (u32)(h * 32) + aKl;
            u32 sw = ((ar & 7) << 4);
            ldsm4(aqh, sb + AT_QH + (off ^ sw));
            ldsm4(aql, sb + AT_QL + (off ^ sw));

            float s[8][4];
#pragma unroll
            for (int nt = 0; nt < 8; nt++)
#pragma unroll
                for (int e = 0; e < 4; e++) s[nt][e] = 0.0f;
#pragma unroll
            for (int np = 0; np < 4; np++) {
                mma16816(s[np * 2], aqh, kbh[np][0], kbh[np][1]);
                mma16816(s[np * 2], aql, kbh[np][0], kbh[np][1]);
                mma16816(s[np * 2], aqh, kbl[np][0], kbl[np][1]);
                mma16816(s[np * 2 + 1], aqh, kbh[np][2], kbh[np][3]);
                mma16816(s[np * 2 + 1], aql, kbh[np][2], kbh[np][3]);
                mma16816(s[np * 2 + 1], aqh, kbl[np][2], kbl[np][3]);
            }
            // softmax rows (mt*16+g) and (+8)
            float m0 = -1e30f, m1 = -1e30f;
#pragma unroll
            for (int nt = 0; nt < 8; nt++) {
                m0 = fmaxf(m0, fmaxf(s[nt][0], s[nt][1]));
                m1 = fmaxf(m1, fmaxf(s[nt][2], s[nt][3]));
            }
            m0 = fmaxf(m0, __shfl_xor_sync(0xffffffff, m0, 1));
            m0 = fmaxf(m0, __shfl_xor_sync(0xffffffff, m0, 2));
            m1 = fmaxf(m1, __shfl_xor_sync(0xffffffff, m1, 1));
            m1 = fmaxf(m1, __shfl_xor_sync(0xffffffff, m1, 2));
            float s0 = 0.f, s1 = 0.f;
#pragma unroll
            for (int nt = 0; nt < 8; nt++) {
                s[nt][0] = __expf(s[nt][0] - m0); s0 += s[nt][0];
                s[nt][1] = __expf(s[nt][1] - m0); s0 += s[nt][1];
                s[nt][2] = __expf(s[nt][2] - m1); s1 += s[nt][2];
                s[nt][3] = __expf(s[nt][3] - m1); s1 += s[nt][3];
            }
            s0 += __shfl_xor_sync(0xffffffff, s0, 1);
            s0 += __shfl_xor_sync(0xffffffff, s0, 2);
            s1 += __shfl_xor_sync(0xffffffff, s1, 1);
            s1 += __shfl_xor_sync(0xffffffff, s1, 2);
            float i0 = 1.0f / s0, i1 = 1.0f / s1;

            float o[2][4];
#pragma unroll
            for (int nt = 0; nt < 2; nt++)
#pragma unroll
                for (int e = 0; e < 4; e++) o[nt][e] = 0.0f;
#pragma unroll
            for (int ks = 0; ks < 4; ks++) {
                u32 ph[4], pl[4];
                split2(s[2 * ks][0], s[2 * ks][1], ph[0], pl[0]);
                split2(s[2 * ks][2], s[2 * ks][3], ph[1], pl[1]);
                split2(s[2 * ks + 1][0], s[2 * ks + 1][1], ph[2], pl[2]);
                split2(s[2 * ks + 1][2], s[2 * ks + 1][3], ph[3], pl[3]);
                mma16816(o[0], ph, vbh[ks][0], vbh[ks][1]);
                mma16816(o[0], pl, vbh[ks][0], vbh[ks][1]);
                mma16816(o[0], ph, vbl[ks][0], vbl[ks][1]);
                mma16816(o[1], ph, vbh[ks][2], vbh[ks][3]);
                mma16816(o[1], pl, vbh[ks][2], vbh[ks][3]);
                mma16816(o[1], ph, vbl[ks][2], vbl[ks][3]);
            }
            // scale + store O hi/lo to x planes
            int r0 = mt * 16 + g, r1 = r0 + 8;
            u32 sw0 = ((u32)(r0 & 7) << 4), sw1 = ((u32)(r1 & 7) << 4);
#pragma unroll
            for (int nt = 0; nt < 2; nt++) {
                int dc = h * 16 + nt * 8 + t * 2;
                u32 h01, l01, h23, l23;
                split2(o[nt][0] * i0, o[nt][1] * i0, h01, l01);
                split2(o[nt][2] * i1, o[nt][3] * i1, h23, l23);
                u32 o0 = ((u32)(r0 * 128 + dc * 2)) ^ sw0;
                u32 o1 = ((u32)(r1 * 128 + dc * 2)) ^ sw1;
                sts32(sb + AT_XH + o0, h01); sts32(sb + AT_XL + o0, l01);
                sts32(sb + AT_XH + o1, h23); sts32(sb + AT_XL + o1, l23);
            }
        }
    }
    CPASYNC_WAIT0();
    __syncthreads();

    // ---- phase 3: proj GEMM (3-term), warp = m-tile; wp lives in vt planes --
    {
        float c[8][4];
#pragma unroll
        for (int nt = 0; nt < 8; nt++)
#pragma unroll
            for (int e = 0; e < 4; e++) c[nt][e] = 0.0f;
#pragma unroll
        for (int ks = 0; ks < 4; ks++) {
            u32 ah[4], al[4];
            u32 ar = (u32)(w * 16 + aRow);
            u32 off = ar * 128 + (u32)(ks * 32) + aKl;
            u32 sw = ((ar & 7) << 4);
            ldsm4(ah, sb + AT_XH + (off ^ sw));
            ldsm4(al, sb + AT_XL + (off ^ sw));
#pragma unroll
            for (int np = 0; np < 4; np++) {
                u32 bh[4], bl[4];
                u32 nr = (u32)(np * 16 + bRow);
                u32 boff = nr * 128 + (u32)(ks * 32) + bKl;
                u32 bsw = ((nr & 7) << 4);
                ldsm4(bh, sb + AT_VTH + (boff ^ bsw));
                ldsm4(bl, sb + AT_VTL + (boff ^ bsw));
                mma16816(c[np * 2], ah, bh[0], bh[1]);
                mma16816(c[np * 2], al, bh[0], bh[1]);
                mma16816(c[np * 2], ah, bl[0], bl[1]);
                mma16816(c[np * 2 + 1], ah, bh[2], bh[3]);
                mma16816(c[np * 2 + 1], al, bh[2], bh[3]);
                mma16816(c[np * 2 + 1], ah, bl[2], bl[3]);
            }
        }
        // epilogue: bias + write
#pragma unroll
        for (int nt = 0; nt < 8; nt++) {
            int cc = nt * 8 + t * 2;
            float b0 = __ldg(projb + cc), b1 = __ldg(projb + cc + 1);
#pragma unroll
            for (int rh = 0; rh < 2; rh++) {
                int tok = w * 16 + g + rh * 8;
                int ty = tok >> 3, tx = tok & 7;
                float v0 = c[nt][rh * 2] + b0, v1 = c[nt][rh * 2 + 1] + b1;
                if (to_h16) {
                    int gy = wy * 8 + ty, gx = wx * 8 + tx;
                    __half* dst = g_h16 +
                        ((size_t)((b * 130 + gy + 1) * 130 + gx + 1)) * 64 + cc;
                    *(__half2*)dst = __floats2half2_rn(v0, v1);
                } else {
                    float* dst = g_buf1 + base + (ty * 128 + tx) * 64 + cc;
                    dst[0] = v0; dst[1] = v1;
                }
            }
        }
    }
}

// ---------------------------------------------------------------------------
// Layer 1 conv on the tensor pipe via mma.sync (m16n8k16 f16 -> f32).
// ---------------------------------------------------------------------------
#define L1_A_OFF 0
#define L1_A_BYTES (390 * 128)
#define L1_B0 L1_A_BYTES
#define L1_B_BYTES (320 * 128)
#define L1_B1 (L1_B0 + L1_B_BYTES)
#define L1_SMEM_TOTAL (L1_B1 + L1_B_BYTES)   // 131840

__device__ __forceinline__ void l1_load_B(u32 sB, int tap, int tid) {
    if (tid < 320) {
        const __half* src = g_w1h + (size_t)(tap * 320 + tid) * 64;
        u32 row = tid * 128;
        u32 sw = (u32)((tid & 7) << 4);
#pragma unroll
        for (int i = 0; i < 8; i++)
            cp16(sB + ((row + i * 16) ^ sw), (const char*)src + i * 16);
    }
}

__global__ __launch_bounds__(512, 1) void layer1_tc(const float* __restrict__ cb) {
    extern __shared__ char smem[];
    u32 sb = smem_u32(smem);
    int tid = threadIdx.x, lane = tid & 31, warp = tid >> 5;
    int wm = warp & 3, wn = warp >> 2;
    int tile = blockIdx.x;
    int b = tile >> 7, y = tile & 127;

    if (tid < 390) {
        int rowIdx = tid / 130, col = tid % 130;
        const __half* src = g_h16 +
            ((size_t)((b * 130 + y + rowIdx) * 130 + col)) * 64;
        u32 row = (u32)tid * 128;
        u32 sw = (u32)((tid & 7) << 4);
#pragma unroll
        for (int i = 0; i < 8; i++)
            cp16(sb + L1_A_OFF + ((row + i * 16) ^ sw), (const char*)src + i * 16);
    }
    l1_load_B(sb + L1_B0, 0, tid);
    CPASYNC_COMMIT();
    CPASYNC_WAIT0();
    __syncthreads();

    float c[2][5][2][4];
#pragma unroll
    for (int mi = 0; mi < 2; mi++)
#pragma unroll
        for (int g5 = 0; g5 < 5; g5++)
#pragma unroll
            for (int nt = 0; nt < 2; nt++)
#pragma unroll
                for (int e = 0; e < 4; e++) c[mi][g5][nt][e] = 0.0f;

    int arow = wm * 32 + (lane & 7) + 8 * ((lane >> 3) & 1);
    u32 aklane = (u32)(16 * (lane >> 4));
    u32 bkl = (u32)(((lane >> 3) & 1) * 16);
    int bnrow_base = wn * 16 + ((lane >> 4) & 1) * 8 + (lane & 7);
    u32 bswz = (u32)((lane & 7) << 4);

#pragma unroll 1
    for (int tap = 0; tap < 9; tap++) {
        u32 Bb = sb + ((tap & 1) ? L1_B1 : L1_B0);
        if (tap < 8) {
            l1_load_B(sb + ((tap & 1) ? L1_B0 : L1_B1), tap + 1, tid);
            CPASYNC_COMMIT();
        }
        int dy = tap / 3, dx = tap % 3;
        int br0 = dy * 130 + arow + dx;
#pragma unroll
        for (int ks = 0; ks < 4; ks++) {
            u32 a[2][4];
#pragma unroll
            for (int mi = 0; mi < 2; mi++) {
                u32 br = (u32)(br0 + mi * 16);
                u32 off = br * 128 + (u32)(ks * 32) + aklane;
                ldsm4(a[mi], sb + L1_A_OFF + (off ^ ((br & 7) << 4)));
            }
#pragma unroll
            for (int g5 = 0; g5 < 5; g5++) {
                u32 bfr[4];
                u32 nrow = (u32)(g5 * 64 + bnrow_base);
                u32 off = nrow * 128 + (u32)(ks * 32) + bkl;
                ldsm4(bfr, Bb + (off ^ bswz));
#pragma unroll
                for (int mi = 0; mi < 2; mi++) {
                    mma16816(c[mi][g5][0], a[mi], bfr[0], bfr[1]);
                    mma16816(c[mi][g5][1], a[mi], bfr[2], bfr[3]);
                }
            }
        }
        if (tap < 8) { CPASYNC_WAIT0(); }
        __syncthreads();
    }

    int q = lane & 3, gr = lane >> 2;
    int ocB = wn * 16;
#pragma unroll
    for (int mi = 0; mi < 2; mi++) {
#pragma unroll
        for (int rh = 0; rh < 2; rh++) {
            int x = wm * 32 + mi * 16 + gr + rh * 8;
            float* orow = g_buf0 + ((size_t)((b * 128 + y) * 128 + x)) * 64;
#pragma unroll
            for (int nt = 0; nt < 2; nt++) {
#pragma unroll
                for (int e = 0; e < 2; e++) {
                    int oc = ocB + nt * 8 + q * 2 + e;
                    int ai = rh * 2 + e;
                    float ci = c[mi][0][nt][ai];
                    float co = c[mi][1][nt][ai];
                    float cg = c[mi][2][nt][ai];
                    float px = c[mi][3][nt][ai];
                    float py = c[mi][4][nt][ai];
                    float ig = sigm(ci + px + __ldg(cb + oc));
                    float og = sigm(co + py + __ldg(cb + 128 + oc));
                    float gg = tanhf(cg + py + __ldg(cb + 192 + oc));
                    orow[oc] = og * tanhf(ig * gg);
                }
            }
        }
    }
}

// ---------------------------------------------------------------------------
// Output 1x1 conv
// ---------------------------------------------------------------------------
__global__ __launch_bounds__(256) void out_conv(const float* __restrict__ ow,
                                                const float* __restrict__ ob,
                                                float* __restrict__ out) {
    int p = blockIdx.x * 256 + threadIdx.x;
    const float4* hv = (const float4*)(g_buf1 + ((size_t)p << 6));
    float acc = 0.0f;
#pragma unroll
    for (int k = 0; k < 16; k++) {
        float4 a = hv[k];
        float4 w = __ldg(((const float4*)ow) + k);
        acc += a.x * w.x + a.y * w.y + a.z * w.z + a.w * w.w;
    }
    out[p] = acc + __ldg(ob);
}

// ---------------------------------------------------------------------------
extern "C" void kernel_launch(void* const* d_in, const int* in_sizes, int n_in,
                              void* d_out, int out_size) {
    const float* x      = (const float*)d_in[0];
    const float* cw0    = (const float*)d_in[1];
    const float* cb0    = (const float*)d_in[2];
    const float* pxw0   = (const float*)d_in[3];
    const float* pyw0   = (const float*)d_in[4];
    const float* qkvw0  = (const float*)d_in[5];
    const float* projw0 = (const float*)d_in[6];
    const float* projb0 = (const float*)d_in[7];
    const float* cw1    = (const float*)d_in[8];
    const float* cb1    = (const float*)d_in[9];
    const float* pxw1   = (const float*)d_in[10];
    const float* pyw1   = (const float*)d_in[11];
    const float* qkvw1  = (const float*)d_in[12];
    const float* projw1 = (const float*)d_in[13];
    const float* projb1 = (const float*)d_in[14];
    const float* outw   = (const float*)d_in[15];
    const float* outb   = (const float*)d_in[16];
    float* out = (float*)d_out;

    cudaFuncSetAttribute(win_attn_tc, cudaFuncAttributeMaxDynamicSharedMemorySize,
                         AT_SMEM);
    cudaFuncSetAttribute(layer1_tc, cudaFuncAttributeMaxDynamicSharedMemorySize,
                         L1_SMEM_TOTAL);

    repack_w1h<<<720, 256>>>(cw1, pxw1, pyw1);
    repack_attn_h<<<48, 256>>>(qkvw0, projw0, qkvw1, projw1);
    zero_h16_borders<<<1057, 256>>>();
    layer0_gates<<<1024, 256>>>(x, cw0, cb0, pxw0, pyw0);            // -> buf0
    win_attn_tc<<<4096, 128, AT_SMEM>>>(0, projb0, 1);               // buf0 -> h16
    layer1_tc<<<2048, 512, L1_SMEM_TOTAL>>>(cb1);                    // h16 -> buf0
    win_attn_tc<<<4096, 128, AT_SMEM>>>(1, projb1, 0);               // buf0 -> buf1
    out_conv<<<1024, 256>>>(outw, outb, out);                        // buf1 -> d_out
}

// round 9
// speedup vs baseline: 4.1842x; 1.1099x over previous
#include <cuda_runtime.h>
#include <cuda_fp16.h>
#include <math.h>
#include <stdint.h>

#define BATCH 16
#define HDIM 128
#define WDIM 128
#define HID 64

typedef uint32_t u32;
typedef uint16_t u16;

// layer-0 output h (NHWC fp32); consumed by attention pass 0
__device__ __align__(16) float g_buf0[BATCH * HDIM * WDIM * HID];
// padded f16 activations for layer-1 conv: [16][130][130][64]
__device__ __align__(16) __half g_h16[BATCH * 130 * 130 * HID];
// f16 layer-1 weights: [tap 9][gate*64+oc 320][cin 64]
__device__ __align__(16) __half g_w1h[9 * 320 * 64];
// f16 attention weights hi/lo (Markidis split): per layer qkv [192][64], proj [64][64]
__device__ __align__(16) __half g_wqh[2][192 * 64];
__device__ __align__(16) __half g_wql[2][192 * 64];
__device__ __align__(16) __half g_wph[2][64 * 64];
__device__ __align__(16) __half g_wpl[2][64 * 64];

__device__ __forceinline__ float sigm(float v) {
    return __fdividef(1.0f, 1.0f + __expf(-v));
}
__device__ __forceinline__ float ftanh(float v) {
    return 1.0f - __fdividef(2.0f, __expf(2.0f * v) + 1.0f);
}

// ===================== sm_80+ tensor helpers (no 'a' target) ================
__device__ __forceinline__ u32 smem_u32(const void* p) {
    u32 a;
    asm("{ .reg .u64 t; cvta.to.shared.u64 t, %1; cvt.u32.u64 %0, t; }"
        : "=r"(a) : "l"(p));
    return a;
}
__device__ __forceinline__ void cp16(u32 dst, const void* src) {
    asm volatile("cp.async.cg.shared.global [%0], [%1], 16;" :: "r"(dst), "l"(src));
}
#define CPASYNC_COMMIT() asm volatile("cp.async.commit_group;" ::: "memory")
#define CPASYNC_WAIT0()  asm volatile("cp.async.wait_group 0;" ::: "memory")

__device__ __forceinline__ void ldsm4(u32* r, u32 a) {
    asm volatile("ldmatrix.sync.aligned.m8n8.x4.shared.b16 {%0,%1,%2,%3}, [%4];"
                 : "=r"(r[0]), "=r"(r[1]), "=r"(r[2]), "=r"(r[3]) : "r"(a));
}
__device__ __forceinline__ void mma16816(float* c, const u32* a, u32 b0, u32 b1) {
    asm volatile(
        "mma.sync.aligned.m16n8k16.row.col.f32.f16.f16.f32 "
        "{%0,%1,%2,%3}, {%4,%5,%6,%7}, {%8,%9}, {%0,%1,%2,%3};"
        : "+f"(c[0]), "+f"(c[1]), "+f"(c[2]), "+f"(c[3])
        : "r"(a[0]), "r"(a[1]), "r"(a[2]), "r"(a[3]), "r"(b0), "r"(b1));
}
__device__ __forceinline__ u32 pk2(float lo, float hi) {   // {lo | hi<<16}
    u32 r;
    asm("cvt.rn.f16x2.f32 %0, %1, %2;" : "=r"(r) : "f"(hi), "f"(lo));
    return r;
}
// f16 hi/lo split of a float pair
__device__ __forceinline__ void split2(float a, float b, u32& hi, u32& lo) {
    __half ha = __float2half_rn(a), hb = __float2half_rn(b);
    hi = ((u32)__half_as_ushort(hb) << 16) | (u32)__half_as_ushort(ha);
    lo = pk2(a - __half2float(ha), b - __half2float(hb));
}
__device__ __forceinline__ void sts32(u32 addr, u32 v) {
    asm volatile("st.shared.b32 [%0], %1;" :: "r"(addr), "r"(v));
}
__device__ __forceinline__ void sts16(u32 addr, float v) {
    u16 b = __half_as_ushort(__float2half_rn(v));
    asm volatile("st.shared.b16 [%0], %1;" :: "r"(addr), "h"(b) : "memory");
}

// ---------------------------------------------------------------------------
// Repack layer-1 weights to f16: g_w1h[tap][g*64+n][cin]
// ---------------------------------------------------------------------------
__global__ void repack_w1h(const float* __restrict__ cw,
                           const float* __restrict__ pxw,
                           const float* __restrict__ pyw) {
    int idx = blockIdx.x * 256 + threadIdx.x;   // 9*320*64 = 184320
    if (idx >= 9 * 320 * 64) return;
    int tap = idx / (320 * 64);
    int rem = idx % (320 * 64);
    int r = rem / 64, cin = rem % 64;
    int g = r >> 6, n = r & 63;
    float v;
    if (g == 0)      v = cw[(n * 128 + cin) * 9 + tap];
    else if (g == 1) v = cw[((128 + n) * 128 + cin) * 9 + tap];
    else if (g == 2) v = cw[((192 + n) * 128 + cin) * 9 + tap];
    else if (g == 3) v = pxw[(n * 64 + cin) * 9 + tap];
    else             v = pyw[(n * 64 + cin) * 9 + tap];
    g_w1h[idx] = __float2half_rn(v);
}

// repack attention weights (both layers) to f16 hi/lo
__global__ void repack_attn_h(const float* __restrict__ q0, const float* __restrict__ p0,
                              const float* __restrict__ q1, const float* __restrict__ p1) {
    int idx = blockIdx.x * 256 + threadIdx.x;
    if (idx < 192 * 64) {
        float v0 = q0[idx], v1 = q1[idx];
        __half h0 = __float2half_rn(v0), h1 = __float2half_rn(v1);
        g_wqh[0][idx] = h0; g_wql[0][idx] = __float2half_rn(v0 - __half2float(h0));
        g_wqh[1][idx] = h1; g_wql[1][idx] = __float2half_rn(v1 - __half2float(h1));
    }
    if (idx < 64 * 64) {
        float v0 = p0[idx], v1 = p1[idx];
        __half h0 = __float2half_rn(v0), h1 = __float2half_rn(v1);
        g_wph[0][idx] = h0; g_wpl[0][idx] = __float2half_rn(v0 - __half2float(h0));
        g_wph[1][idx] = h1; g_wpl[1][idx] = __float2half_rn(v1 - __half2float(h1));
    }
}

// zero the 1-pixel border of the padded f16 buffer
__global__ void zero_h16_borders() {
    int p = blockIdx.x * 256 + threadIdx.x;     // 16*130*130 = 270400 pixels
    if (p >= BATCH * 130 * 130) return;
    int bp = p % (130 * 130);
    int yy = bp / 130, xx = bp % 130;
    if (yy == 0 || yy == 129 || xx == 0 || xx == 129) {
        uint4* d = (uint4*)(g_h16 + (size_t)p * 64);
        uint4 z = {0, 0, 0, 0};
#pragma unroll
        for (int i = 0; i < 8; i++) d[i] = z;
    }
}

// ---------------------------------------------------------------------------
// Layer 0 fused gates v2: CIN=1, coalesced output.
// Thread = one pixel. Weights [c][48] (g*9+tap, 45 used) -> 12 broadcast
// LDS.128 per channel. Output staged in smem [tid][20] (STS.128, conflict-
// free) and flushed coalesced in 16-channel chunks (STG.128, 8 lines/warp).
// ---------------------------------------------------------------------------
__global__ __launch_bounds__(256) void layer0_gates(
    const float* __restrict__ x, const float* __restrict__ cw,
    const float* __restrict__ cb, const float* __restrict__ pxw,
    const float* __restrict__ pyw) {
    __shared__ float s_w[64 * 48];
    __shared__ float s_b[3][64];
    __shared__ float s_out[256 * 20];
    int tid = threadIdx.x;
    for (int i = tid; i < 64 * 45; i += 256) {
        int c = i / 45, j = i % 45;
        int g = j / 9, tap = j % 9;
        float v;
        if (g == 0)      v = cw[c * 585 + tap];
        else if (g == 1) v = cw[(128 + c) * 585 + tap];
        else if (g == 2) v = cw[(192 + c) * 585 + tap];
        else if (g == 3) v = pxw[c * 9 + tap];
        else             v = pyw[c * 9 + tap];
        s_w[c * 48 + j] = v;
    }
    if (tid < 64) {
        s_b[0][tid] = cb[tid];
        s_b[1][tid] = cb[128 + tid];
        s_b[2][tid] = cb[192 + tid];
    }
    __syncthreads();

    int p = blockIdx.x * 256 + tid;
    int b = p >> 14, y = (p >> 7) & 127, xc = p & 127;
    float pv[9];
#pragma unroll
    for (int ky = 0; ky < 3; ky++)
#pragma unroll
        for (int kx = 0; kx < 3; kx++) {
            int gy = y + ky - 1, gx = xc + kx - 1;
            pv[ky * 3 + kx] = (gy >= 0 && gy < 128 && gx >= 0 && gx < 128)
                                  ? x[(b << 14) + gy * 128 + gx] : 0.0f;
        }

#pragma unroll 1
    for (int chunk = 0; chunk < 4; chunk++) {
        float4 ov;
#pragma unroll
        for (int cc = 0; cc < 16; cc++) {
            int c = chunk * 16 + cc;
            float wv[48];
            const float4* w4 = (const float4*)(s_w + c * 48);
#pragma unroll
            for (int q = 0; q < 12; q++) {
                float4 t4 = w4[q];
                wv[q * 4 + 0] = t4.x; wv[q * 4 + 1] = t4.y;
                wv[q * 4 + 2] = t4.z; wv[q * 4 + 3] = t4.w;
            }
            float aci = 0.f, aco = 0.f, acg = 0.f, apx = 0.f, apy = 0.f;
#pragma unroll
            for (int tap = 0; tap < 9; tap++) {
                float a = pv[tap];
                aci += a * wv[tap];
                aco += a * wv[9 + tap];
                acg += a * wv[18 + tap];
                apx += a * wv[27 + tap];
                apy += a * wv[36 + tap];
            }
            float ig = sigm(aci + apx + s_b[0][c]);
            float og = sigm(aco + apy + s_b[1][c]);
            float gg = ftanh(acg + apy + s_b[2][c]);
            float r = og * ftanh(ig * gg);
            int e = cc & 3;
            if (e == 0) ov.x = r; else if (e == 1) ov.y = r;
            else if (e == 2) ov.z = r;
            else {
                ov.w = r;
                *(float4*)(s_out + tid * 20 + (cc >> 2) * 4) = ov;
            }
        }
        __syncthreads();
        // coalesced flush: 1024 float4 = 256 px x 16 ch
#pragma unroll
        for (int it = 0; it < 4; it++) {
            int i = it * 256 + tid;
            int pp = i >> 2, k = i & 3;
            float4 v4 = *(const float4*)(s_out + pp * 20 + k * 4);
            *(float4*)(g_buf0 +
                       ((size_t)(blockIdx.x * 256 + pp)) * 64 + chunk * 16 + k * 4) = v4;
        }
        __syncthreads();
    }
}

// ---------------------------------------------------------------------------
// Window attention on mma.sync with f16 hi/lo error compensation.
// Block = 1 window, 4 warps. 3-term GEMMs: Ah*Bh + Al*Bh + Ah*Bl.
// to_h16=1: write padded f16 g_h16. to_h16=0: fused 1x1 out-conv -> out.
// ---------------------------------------------------------------------------
#define AT_XH 0
#define AT_XL 8192
#define AT_QH 16384
#define AT_QL 24576
#define AT_KH 32768
#define AT_KL 40960
#define AT_VTH 49152
#define AT_VTL 57344
#define AT_WQH 65536
#define AT_WQL 90112
#define AT_SMEM 114688

__global__ __launch_bounds__(128) void win_attn_tc(
    int layer, const float* __restrict__ projb,
    const float* __restrict__ outw, const float* __restrict__ outb,
    float* __restrict__ out, int to_h16) {
    extern __shared__ char smem[];
    u32 sb = smem_u32(smem);
    int tid = threadIdx.x, lane = tid & 31, w = tid >> 5;
    int wid = blockIdx.x;
    int b = wid >> 8, wy = (wid >> 4) & 15, wx = wid & 15;
    int base = ((b * 128 + wy * 8) * 128 + wx * 8) * 64;

    // ---- stage qkv weights hi/lo + x (fp32 -> f16 hi/lo) ----
    for (int r = tid; r < 192; r += 128) {
        const __half* sh = g_wqh[layer] + r * 64;
        const __half* sl = g_wql[layer] + r * 64;
        u32 row = (u32)r * 128, sw = (u32)((r & 7) << 4);
#pragma unroll
        for (int i = 0; i < 8; i++) {
            cp16(sb + AT_WQH + ((row + i * 16) ^ sw), (const char*)sh + i * 16);
            cp16(sb + AT_WQL + ((row + i * 16) ^ sw), (const char*)sl + i * 16);
        }
    }
    CPASYNC_COMMIT();
    {
        int row = tid >> 1, half = tid & 1;           // token row, 32-col half
        int ty = row >> 3, tx = row & 7;
        const float* src = g_buf0 + base + (ty * 128 + tx) * 64 + half * 32;
        u32 sw = (u32)((row & 7) << 4);
#pragma unroll
        for (int j = 0; j < 8; j++) {
            float4 a = *(const float4*)(src + j * 4);
            u32 byte0 = (u32)(row * 128 + half * 64 + j * 8);
            u32 h01, l01, h23, l23;
            split2(a.x, a.y, h01, l01);
            split2(a.z, a.w, h23, l23);
            sts32(sb + AT_XH + (byte0 ^ sw), h01);
            sts32(sb + AT_XL + (byte0 ^ sw), l01);
            sts32(sb + AT_XH + ((byte0 + 4) ^ sw), h23);
            sts32(sb + AT_XL + ((byte0 + 4) ^ sw), l23);
        }
    }
    CPASYNC_WAIT0();
    __syncthreads();

    // lane-invariant ldsm address pieces
    int aRow = (lane & 7) + 8 * ((lane >> 3) & 1);
    u32 aKl = (u32)(16 * (lane >> 4));
    int bRow = ((lane >> 4) & 1) * 8 + (lane & 7);
    u32 bKl = (u32)(((lane >> 3) & 1) * 16);
    int g = lane >> 2, t = lane & 3;

    // ---- phase 1: QKV GEMM (3-term). warp w -> out cols [w*48, w*48+48) ----
    {
        float c[4][6][4];
#pragma unroll
        for (int mt = 0; mt < 4; mt++)
#pragma unroll
            for (int nt = 0; nt < 6; nt++)
#pragma unroll
                for (int e = 0; e < 4; e++) c[mt][nt][e] = 0.0f;

#pragma unroll
        for (int ks = 0; ks < 4; ks++) {
            u32 ah[4][4], al[4][4];
#pragma unroll
            for (int mt = 0; mt < 4; mt++) {
                u32 ar = (u32)(mt * 16 + aRow);
                u32 off = ar * 128 + (u32)(ks * 32) + aKl;
                u32 sw = ((ar & 7) << 4);
                ldsm4(ah[mt], sb + AT_XH + (off ^ sw));
                ldsm4(al[mt], sb + AT_XL + (off ^ sw));
            }
#pragma unroll
            for (int np = 0; np < 3; np++) {
                u32 bh[4], bl[4];
                u32 nr = (u32)(w * 48 + np * 16 + bRow);
                u32 off = nr * 128 + (u32)(ks * 32) + bKl;
                u32 sw = ((nr & 7) << 4);
                ldsm4(bh, sb + AT_WQH + (off ^ sw));
                ldsm4(bl, sb + AT_WQL + (off ^ sw));
#pragma unroll
                for (int mt = 0; mt < 4; mt++) {
                    mma16816(c[mt][np * 2], ah[mt], bh[0], bh[1]);
                    mma16816(c[mt][np * 2], al[mt], bh[0], bh[1]);
                    mma16816(c[mt][np * 2], ah[mt], bl[0], bl[1]);
                    mma16816(c[mt][np * 2 + 1], ah[mt], bh[2], bh[3]);
                    mma16816(c[mt][np * 2 + 1], al[mt], bh[2], bh[3]);
                    mma16816(c[mt][np * 2 + 1], ah[mt], bl[2], bl[3]);
                }
            }
        }
        // store Q (x0.25), K, V^T as f16 hi/lo
#pragma unroll
        for (int mt = 0; mt < 4; mt++) {
#pragma unroll
            for (int nt = 0; nt < 6; nt++) {
                int nc = w * 48 + nt * 8 + t * 2;
                int r0 = mt * 16 + g, r1 = r0 + 8;
                float v0 = c[mt][nt][0], v1 = c[mt][nt][1];
                float v2 = c[mt][nt][2], v3 = c[mt][nt][3];
                u32 sw0 = ((u32)(r0 & 7) << 4), sw1 = ((u32)(r1 & 7) << 4);
                if (nc < 64) {
                    u32 h01, l01, h23, l23;
                    split2(v0 * 0.25f, v1 * 0.25f, h01, l01);
                    split2(v2 * 0.25f, v3 * 0.25f, h23, l23);
                    u32 o0 = ((u32)(r0 * 128 + nc * 2)) ^ sw0;
                    u32 o1 = ((u32)(r1 * 128 + nc * 2)) ^ sw1;
                    sts32(sb + AT_QH + o0, h01); sts32(sb + AT_QL + o0, l01);
                    sts32(sb + AT_QH + o1, h23); sts32(sb + AT_QL + o1, l23);
                } else if (nc < 128) {
                    int kc = nc - 64;
                    u32 h01, l01, h23, l23;
                    split2(v0, v1, h01, l01);
                    split2(v2, v3, h23, l23);
                    u32 o0 = ((u32)(r0 * 128 + kc * 2)) ^ sw0;
                    u32 o1 = ((u32)(r1 * 128 + kc * 2)) ^ sw1;
                    sts32(sb + AT_KH + o0, h01); sts32(sb + AT_KL + o0, l01);
                    sts32(sb + AT_KH + o1, h23); sts32(sb + AT_KL + o1, l23);
                } else {
                    int d0 = nc - 128, d1 = d0 + 1;
                    u32 s0 = (u32)((d0 & 7) << 4), s1 = (u32)((d1 & 7) << 4);
                    float vv[4] = {v0, v1, v2, v3};
                    int dd[4] = {d0, d1, d0, d1};
                    int rr[4] = {r0, r0, r1, r1};
                    u32 ss[4] = {s0, s1, s0, s1};
#pragma unroll
                    for (int e = 0; e < 4; e++) {
                        __half h = __float2half_rn(vv[e]);
                        float rl = vv[e] - __half2float(h);
                        u32 off = ((u32)(dd[e] * 128 + rr[e] * 2)) ^ ss[e];
                        sts16(sb + AT_VTH + off, vv[e]);
                        sts16(sb + AT_VTL + off, rl);
                    }
                }
            }
        }
    }
    __syncthreads();

    // ---- phase 2: attention, warp = head ----
    {
        int h = w;
        u32 kbh[4][4], kbl[4][4], vbh[4][4], vbl[4][4];
#pragma unroll
        for (int np = 0; np < 4; np++) {
            u32 nr = (u32)(np * 16 + bRow);
            u32 off = nr * 128 + (u32)(h * 32) + bKl;
            u32 sw = ((nr & 7) << 4);
            ldsm4(kbh[np], sb + AT_KH + (off ^ sw));
            ldsm4(kbl[np], sb + AT_KL + (off ^ sw));
        }
#pragma unroll
        for (int ks = 0; ks < 4; ks++) {
            u32 nr = (u32)(h * 16 + bRow);
            u32 off = nr * 128 + (u32)(ks * 32) + bKl;
            u32 sw = ((nr & 7) << 4);
            ldsm4(vbh[ks], sb + AT_VTH + (off ^ sw));
            ldsm4(vbl[ks], sb + AT_VTL + (off ^ sw));
        }
        __syncthreads();   // all warps hold K/V fragments; vt planes now free
        // stage proj weights into the vt planes (overlap with compute)
        {
            int r = tid & 63;
            const __half* src = (tid < 64) ? (g_wph[layer] + r * 64)
                                           : (g_wpl[layer] + r * 64);
            u32 dstb = (tid < 64) ? (sb + AT_VTH) : (sb + AT_VTL);
            u32 row = (u32)r * 128, sw = (u32)((r & 7) << 4);
#pragma unroll
            for (int i = 0; i < 8; i++)
                cp16(dstb + ((row + i * 16) ^ sw), (const char*)src + i * 16);
            CPASYNC_COMMIT();
        }

#pragma unroll
        for (int mt = 0; mt < 4; mt++) {
            u32 aqh[4], aql[4];
            u32 ar = (u32)(mt * 16 + aRow);
            u32 off = ar * 128 + (u32)(h * 32) + aKl;
            u32 sw = ((ar & 7) << 4);
            ldsm4(aqh, sb + AT_QH + (off ^ sw));
            ldsm4(aql, sb + AT_QL + (off ^ sw));

            float s[8][4];
#pragma unroll
            for (int nt = 0; nt < 8; nt++)
#pragma unroll
                for (int e = 0; e < 4; e++) s[nt][e] = 0.0f;
#pragma unroll
            for (int np = 0; np < 4; np++) {
                mma16816(s[np * 2], aqh, kbh[np][0], kbh[np][1]);
                mma16816(s[np * 2], aql, kbh[np][0], kbh[np][1]);
                mma16816(s[np * 2], aqh, kbl[np][0], kbl[np][1]);
                mma16816(s[np * 2 + 1], aqh, kbh[np][2], kbh[np][3]);
                mma16816(s[np * 2 + 1], aql, kbh[np][2], kbh[np][3]);
                mma16816(s[np * 2 + 1], aqh, kbl[np][2], kbl[np][3]);
            }
            // softmax rows (mt*16+g) and (+8)
            float m0 = -1e30f, m1 = -1e30f;
#pragma unroll
            for (int nt = 0; nt < 8; nt++) {
                m0 = fmaxf(m0, fmaxf(s[nt][0], s[nt][1]));
                m1 = fmaxf(m1, fmaxf(s[nt][2], s[nt][3]));
            }
            m0 = fmaxf(m0, __shfl_xor_sync(0xffffffff, m0, 1));
            m0 = fmaxf(m0, __shfl_xor_sync(0xffffffff, m0, 2));
            m1 = fmaxf(m1, __shfl_xor_sync(0xffffffff, m1, 1));
            m1 = fmaxf(m1, __shfl_xor_sync(0xffffffff, m1, 2));
            float s0 = 0.f, s1 = 0.f;
#pragma unroll
            for (int nt = 0; nt < 8; nt++) {
                s[nt][0] = __expf(s[nt][0] - m0); s0 += s[nt][0];
                s[nt][1] = __expf(s[nt][1] - m0); s0 += s[nt][1];
                s[nt][2] = __expf(s[nt][2] - m1); s1 += s[nt][2];
                s[nt][3] = __expf(s[nt][3] - m1); s1 += s[nt][3];
            }
            s0 += __shfl_xor_sync(0xffffffff, s0, 1);
            s0 += __shfl_xor_sync(0xffffffff, s0, 2);
            s1 += __shfl_xor_sync(0xffffffff, s1, 1);
            s1 += __shfl_xor_sync(0xffffffff, s1, 2);
            float i0 = 1.0f / s0, i1 = 1.0f / s1;

            float o[2][4];
#pragma unroll
            for (int nt = 0; nt < 2; nt++)
#pragma unroll
                for (int e = 0; e < 4; e++) o[nt][e] = 0.0f;
#pragma unroll
            for (int ks = 0; ks < 4; ks++) {
                u32 ph[4], pl[4];
                split2(s[2 * ks][0], s[2 * ks][1], ph[0], pl[0]);
                split2(s[2 * ks][2], s[2 * ks][3], ph[1], pl[1]);
                split2(s[2 * ks + 1][0], s[2 * ks + 1][1], ph[2], pl[2]);
                split2(s[2 * ks + 1][2], s[2 * ks + 1][3], ph[3], pl[3]);
                mma16816(o[0], ph, vbh[ks][0], vbh[ks][1]);
                mma16816(o[0], pl, vbh[ks][0], vbh[ks][1]);
                mma16816(o[0], ph, vbl[ks][0], vbl[ks][1]);
                mma16816(o[1], ph, vbh[ks][2], vbh[ks][3]);
                mma16816(o[1], pl, vbh[ks][2], vbh[ks][3]);
                mma16816(o[1], ph, vbl[ks][2], vbl[ks][3]);
            }
            // scale + store O hi/lo to x planes
            int r0 = mt * 16 + g, r1 = r0 + 8;
            u32 sw0 = ((u32)(r0 & 7) << 4), sw1 = ((u32)(r1 & 7) << 4);
#pragma unroll
            for (int nt = 0; nt < 2; nt++) {
                int dc = h * 16 + nt * 8 + t * 2;
                u32 h01, l01, h23, l23;
                split2(o[nt][0] * i0, o[nt][1] * i0, h01, l01);
                split2(o[nt][2] * i1, o[nt][3] * i1, h23, l23);
                u32 o0 = ((u32)(r0 * 128 + dc * 2)) ^ sw0;
                u32 o1 = ((u32)(r1 * 128 + dc * 2)) ^ sw1;
                sts32(sb + AT_XH + o0, h01); sts32(sb + AT_XL + o0, l01);
                sts32(sb + AT_XH + o1, h23); sts32(sb + AT_XL + o1, l23);
            }
        }
    }
    CPASYNC_WAIT0();
    __syncthreads();

    // ---- phase 3: proj GEMM (3-term), warp = m-tile; wp lives in vt planes --
    {
        float c[8][4];
#pragma unroll
        for (int nt = 0; nt < 8; nt++)
#pragma unroll
            for (int e = 0; e < 4; e++) c[nt][e] = 0.0f;
#pragma unroll
        for (int ks = 0; ks < 4; ks++) {
            u32 ah[4], al[4];
            u32 ar = (u32)(w * 16 + aRow);
            u32 off = ar * 128 + (u32)(ks * 32) + aKl;
            u32 sw = ((ar & 7) << 4);
            ldsm4(ah, sb + AT_XH + (off ^ sw));
            ldsm4(al, sb + AT_XL + (off ^ sw));
#pragma unroll
            for (int np = 0; np < 4; np++) {
                u32 bh[4], bl[4];
                u32 nr = (u32)(np * 16 + bRow);
                u32 boff = nr * 128 + (u32)(ks * 32) + bKl;
                u32 bsw = ((nr & 7) << 4);
                ldsm4(bh, sb + AT_VTH + (boff ^ bsw));
                ldsm4(bl, sb + AT_VTL + (boff ^ bsw));
                mma16816(c[np * 2], ah, bh[0], bh[1]);
                mma16816(c[np * 2], al, bh[0], bh[1]);
                mma16816(c[np * 2], ah, bl[0], bl[1]);
                mma16816(c[np * 2 + 1], ah, bh[2], bh[3]);
                mma16816(c[np * 2 + 1], al, bh[2], bh[3]);
                mma16816(c[np * 2 + 1], ah, bl[2], bl[3]);
            }
        }
        if (to_h16) {
            // epilogue: bias + write padded f16
#pragma unroll
            for (int nt = 0; nt < 8; nt++) {
                int cc = nt * 8 + t * 2;
                float b0 = __ldg(projb + cc), b1 = __ldg(projb + cc + 1);
#pragma unroll
                for (int rh = 0; rh < 2; rh++) {
                    int tok = w * 16 + g + rh * 8;
                    int ty = tok >> 3, tx = tok & 7;
                    float v0 = c[nt][rh * 2] + b0, v1 = c[nt][rh * 2 + 1] + b1;
                    int gy = wy * 8 + ty, gx = wx * 8 + tx;
                    __half* dst = g_h16 +
                        ((size_t)((b * 130 + gy + 1) * 130 + gx + 1)) * 64 + cc;
                    *(__half2*)dst = __floats2half2_rn(v0, v1);
                }
            }
        } else {
            // fused 1x1 output conv: out[tok] = sum_c (h1[c]) * outw[c] + outb
            float acc0 = 0.0f, acc1 = 0.0f;
#pragma unroll
            for (int nt = 0; nt < 8; nt++) {
                int cc = nt * 8 + t * 2;
                float b0 = __ldg(projb + cc), b1 = __ldg(projb + cc + 1);
                float w0 = __ldg(outw + cc), w1 = __ldg(outw + cc + 1);
                acc0 += (c[nt][0] + b0) * w0 + (c[nt][1] + b1) * w1;
                acc1 += (c[nt][2] + b0) * w0 + (c[nt][3] + b1) * w1;
            }
            acc0 += __shfl_xor_sync(0xffffffff, acc0, 1);
            acc0 += __shfl_xor_sync(0xffffffff, acc0, 2);
            acc1 += __shfl_xor_sync(0xffffffff, acc1, 1);
            acc1 += __shfl_xor_sync(0xffffffff, acc1, 2);
            if (t == 0) {
                float ob = __ldg(outb);
#pragma unroll
                for (int rh = 0; rh < 2; rh++) {
                    int tok = w * 16 + g + rh * 8;
                    int ty = tok >> 3, tx = tok & 7;
                    int gy = wy * 8 + ty, gx = wx * 8 + tx;
                    out[(b * 128 + gy) * 128 + gx] = (rh ? acc1 : acc0) + ob;
                }
            }
        }
    }
}

// ---------------------------------------------------------------------------
// Layer 1 conv on the tensor pipe via mma.sync (m16n8k16 f16 -> f32).
// ---------------------------------------------------------------------------
#define L1_A_OFF 0
#define L1_A_BYTES (390 * 128)
#define L1_B0 L1_A_BYTES
#define L1_B_BYTES (320 * 128)
#define L1_B1 (L1_B0 + L1_B_BYTES)
#define L1_SMEM_TOTAL (L1_B1 + L1_B_BYTES)   // 131840

__device__ __forceinline__ void l1_load_B(u32 sB, int tap, int tid) {
    if (tid < 320) {
        const __half* src = g_w1h + (size_t)(tap * 320 + tid) * 64;
        u32 row = tid * 128;
        u32 sw = (u32)((tid & 7) << 4);
#pragma unroll
        for (int i = 0; i < 8; i++)
            cp16(sB + ((row + i * 16) ^ sw), (const char*)src + i * 16);
    }
}

__global__ __launch_bounds__(512, 1) void layer1_tc(const float* __restrict__ cb) {
    extern __shared__ char smem[];
    u32 sb = smem_u32(smem);
    int tid = threadIdx.x, lane = tid & 31, warp = tid >> 5;
    int wm = warp & 3, wn = warp >> 2;
    int tile = blockIdx.x;
    int b = tile >> 7, y = tile & 127;

    if (tid < 390) {
        int rowIdx = tid / 130, col = tid % 130;
        const __half* src = g_h16 +
            ((size_t)((b * 130 + y + rowIdx) * 130 + col)) * 64;
        u32 row = (u32)tid * 128;
        u32 sw = (u32)((tid & 7) << 4);
#pragma unroll
        for (int i = 0; i < 8; i++)
            cp16(sb + L1_A_OFF + ((row + i * 16) ^ sw), (const char*)src + i * 16);
    }
    l1_load_B(sb + L1_B0, 0, tid);
    CPASYNC_COMMIT();
    CPASYNC_WAIT0();
    __syncthreads();

    float c[2][5][2][4];
#pragma unroll
    for (int mi = 0; mi < 2; mi++)
#pragma unroll
        for (int g5 = 0; g5 < 5; g5++)
#pragma unroll
            for (int nt = 0; nt < 2; nt++)
#pragma unroll
                for (int e = 0; e < 4; e++) c[mi][g5][nt][e] = 0.0f;

    int arow = wm * 32 + (lane & 7) + 8 * ((lane >> 3) & 1);
    u32 aklane = (u32)(16 * (lane >> 4));
    u32 bkl = (u32)(((lane >> 3) & 1) * 16);
    int bnrow_base = wn * 16 + ((lane >> 4) & 1) * 8 + (lane & 7);
    u32 bswz = (u32)((lane & 7) << 4);

#pragma unroll 1
    for (int tap = 0; tap < 9; tap++) {
        u32 Bb = sb + ((tap & 1) ? L1_B1 : L1_B0);
        if (tap < 8) {
            l1_load_B(sb + ((tap & 1) ? L1_B0 : L1_B1), tap + 1, tid);
            CPASYNC_COMMIT();
        }
        int dy = tap / 3, dx = tap % 3;
        int br0 = dy * 130 + arow + dx;
#pragma unroll
        for (int ks = 0; ks < 4; ks++) {
            u32 a[2][4];
#pragma unroll
            for (int mi = 0; mi < 2; mi++) {
                u32 br = (u32)(br0 + mi * 16);
                u32 off = br * 128 + (u32)(ks * 32) + aklane;
                ldsm4(a[mi], sb + L1_A_OFF + (off ^ ((br & 7) << 4)));
            }
#pragma unroll
            for (int g5 = 0; g5 < 5; g5++) {
                u32 bfr[4];
                u32 nrow = (u32)(g5 * 64 + bnrow_base);
                u32 off = nrow * 128 + (u32)(ks * 32) + bkl;
                ldsm4(bfr, Bb + (off ^ bswz));
#pragma unroll
                for (int mi = 0; mi < 2; mi++) {
                    mma16816(c[mi][g5][0], a[mi], bfr[0], bfr[1]);
                    mma16816(c[mi][g5][1], a[mi], bfr[2], bfr[3]);
                }
            }
        }
        if (tap < 8) { CPASYNC_WAIT0(); }
        __syncthreads();
    }

    int q = lane & 3, gr = lane >> 2;
    int ocB = wn * 16;
#pragma unroll
    for (int mi = 0; mi < 2; mi++) {
#pragma unroll
        for (int rh = 0; rh < 2; rh++) {
            int x = wm * 32 + mi * 16 + gr + rh * 8;
            float* orow = g_buf0 + ((size_t)((b * 128 + y) * 128 + x)) * 64;
#pragma unroll
            for (int nt = 0; nt < 2; nt++) {
#pragma unroll
                for (int e = 0; e < 2; e++) {
                    int oc = ocB + nt * 8 + q * 2 + e;
                    int ai = rh * 2 + e;
                    float ci = c[mi][0][nt][ai];
                    float co = c[mi][1][nt][ai];
                    float cg = c[mi][2][nt][ai];
                    float px = c[mi][3][nt][ai];
                    float py = c[mi][4][nt][ai];
                    float ig = sigm(ci + px + __ldg(cb + oc));
                    float og = sigm(co + py + __ldg(cb + 128 + oc));
                    float gg = ftanh(cg + py + __ldg(cb + 192 + oc));
                    orow[oc] = og * ftanh(ig * gg);
                }
            }
        }
    }
}

// ---------------------------------------------------------------------------
extern "C" void kernel_launch(void* const* d_in, const int* in_sizes, int n_in,
                              void* d_out, int out_size) {
    const float* x      = (const float*)d_in[0];
    const float* cw0    = (const float*)d_in[1];
    const float* cb0    = (const float*)d_in[2];
    const float* pxw0   = (const float*)d_in[3];
    const float* pyw0   = (const float*)d_in[4];
    const float* qkvw0  = (const float*)d_in[5];
    const float* projw0 = (const float*)d_in[6];
    const float* projb0 = (const float*)d_in[7];
    const float* cw1    = (const float*)d_in[8];
    const float* cb1    = (const float*)d_in[9];
    const float* pxw1   = (const float*)d_in[10];
    const float* pyw1   = (const float*)d_in[11];
    const float* qkvw1  = (const float*)d_in[12];
    const float* projw1 = (const float*)d_in[13];
    const float* projb1 = (const float*)d_in[14];
    const float* outw   = (const float*)d_in[15];
    const float* outb   = (const float*)d_in[16];
    float* out = (float*)d_out;

    cudaFuncSetAttribute(win_attn_tc, cudaFuncAttributeMaxDynamicSharedMemorySize,
                         AT_SMEM);
    cudaFuncSetAttribute(layer1_tc, cudaFuncAttributeMaxDynamicSharedMemorySize,
                         L1_SMEM_TOTAL);

    repack_w1h<<<720, 256>>>(cw1, pxw1, pyw1);
    repack_attn_h<<<48, 256>>>(qkvw0, projw0, qkvw1, projw1);
    zero_h16_borders<<<1057, 256>>>();
    layer0_gates<<<1024, 256>>>(x, cw0, cb0, pxw0, pyw0);             // -> buf0
    win_attn_tc<<<4096, 128, AT_SMEM>>>(0, projb0, outw, outb, out, 1); // buf0 -> h16
    layer1_tc<<<2048, 512, L1_SMEM_TOTAL>>>(cb1);                     // h16 -> buf0
    win_attn_tc<<<4096, 128, AT_SMEM>>>(1, projb1, outw, outb, out, 0); // buf0 -> out
}

// round 10
// speedup vs baseline: 4.6078x; 1.1012x over previous
#include <cuda_runtime.h>
#include <cuda_fp16.h>
#include <math.h>
#include <stdint.h>

#define BATCH 16
#define HDIM 128
#define WDIM 128
#define HID 64

typedef uint32_t u32;
typedef uint16_t u16;

// layer-0 output h (NHWC fp32); consumed by attention pass 0
__device__ __align__(16) float g_buf0[BATCH * HDIM * WDIM * HID];
// padded f16 activations for layer-1 conv: [16][130][130][64]
__device__ __align__(16) __half g_h16[BATCH * 130 * 130 * HID];
// f16 layer-1 weights: [tap 9][gate*64+oc 320][cin 64]
__device__ __align__(16) __half g_w1h[9 * 320 * 64];
// f16 attention weights hi/lo (Markidis split): per layer qkv [192][64], proj [64][64]
__device__ __align__(16) __half g_wqh[2][192 * 64];
__device__ __align__(16) __half g_wql[2][192 * 64];
__device__ __align__(16) __half g_wph[2][64 * 64];
__device__ __align__(16) __half g_wpl[2][64 * 64];

__device__ __forceinline__ float sigm(float v) {
    return __fdividef(1.0f, 1.0f + __expf(-v));
}
__device__ __forceinline__ float ftanh(float v) {
    return 1.0f - __fdividef(2.0f, __expf(2.0f * v) + 1.0f);
}

// ===================== sm_80+ tensor helpers (no 'a' target) ================
__device__ __forceinline__ u32 smem_u32(const void* p) {
    u32 a;
    asm("{ .reg .u64 t; cvta.to.shared.u64 t, %1; cvt.u32.u64 %0, t; }"
        : "=r"(a) : "l"(p));
    return a;
}
__device__ __forceinline__ void cp16(u32 dst, const void* src) {
    asm volatile("cp.async.cg.shared.global [%0], [%1], 16;" :: "r"(dst), "l"(src));
}
#define CPASYNC_COMMIT() asm volatile("cp.async.commit_group;" ::: "memory")
#define CPASYNC_WAIT0()  asm volatile("cp.async.wait_group 0;" ::: "memory")

__device__ __forceinline__ void ldsm4(u32* r, u32 a) {
    asm volatile("ldmatrix.sync.aligned.m8n8.x4.shared.b16 {%0,%1,%2,%3}, [%4];"
                 : "=r"(r[0]), "=r"(r[1]), "=r"(r[2]), "=r"(r[3]) : "r"(a));
}
__device__ __forceinline__ void mma16816(float* c, const u32* a, u32 b0, u32 b1) {
    asm volatile(
        "mma.sync.aligned.m16n8k16.row.col.f32.f16.f16.f32 "
        "{%0,%1,%2,%3}, {%4,%5,%6,%7}, {%8,%9}, {%0,%1,%2,%3};"
        : "+f"(c[0]), "+f"(c[1]), "+f"(c[2]), "+f"(c[3])
        : "r"(a[0]), "r"(a[1]), "r"(a[2]), "r"(a[3]), "r"(b0), "r"(b1));
}
__device__ __forceinline__ u32 pk2(float lo, float hi) {   // {lo | hi<<16}
    u32 r;
    asm("cvt.rn.f16x2.f32 %0, %1, %2;" : "=r"(r) : "f"(hi), "f"(lo));
    return r;
}
// f16 hi/lo split of a float pair
__device__ __forceinline__ void split2(float a, float b, u32& hi, u32& lo) {
    __half ha = __float2half_rn(a), hb = __float2half_rn(b);
    hi = ((u32)__half_as_ushort(hb) << 16) | (u32)__half_as_ushort(ha);
    lo = pk2(a - __half2float(ha), b - __half2float(hb));
}
__device__ __forceinline__ void sts32(u32 addr, u32 v) {
    asm volatile("st.shared.b32 [%0], %1;" :: "r"(addr), "r"(v));
}
__device__ __forceinline__ void sts16(u32 addr, float v) {
    u16 b = __half_as_ushort(__float2half_rn(v));
    asm volatile("st.shared.b16 [%0], %1;" :: "r"(addr), "h"(b) : "memory");
}

// ---------------------------------------------------------------------------
// Merged prep: layer-1 weight repack + border zero + attention weight repack
// ---------------------------------------------------------------------------
#define PREP_A (9 * 320 * 64)          // 184320
#define PREP_B (BATCH * 130 * 130)     // 270400
#define PREP_C (192 * 64)              // 12288
#define PREP_D (64 * 64)               // 4096
#define PREP_TOTAL (PREP_A + PREP_B + PREP_C + PREP_D)

__global__ void prep_all(const float* __restrict__ cw,
                         const float* __restrict__ pxw,
                         const float* __restrict__ pyw,
                         const float* __restrict__ q0, const float* __restrict__ p0,
                         const float* __restrict__ q1, const float* __restrict__ p1) {
    int idx = blockIdx.x * 256 + threadIdx.x;
    if (idx < PREP_A) {
        int tap = idx / (320 * 64);
        int rem = idx % (320 * 64);
        int r = rem / 64, cin = rem % 64;
        int g = r >> 6, n = r & 63;
        float v;
        if (g == 0)      v = cw[(n * 128 + cin) * 9 + tap];
        else if (g == 1) v = cw[((128 + n) * 128 + cin) * 9 + tap];
        else if (g == 2) v = cw[((192 + n) * 128 + cin) * 9 + tap];
        else if (g == 3) v = pxw[(n * 64 + cin) * 9 + tap];
        else             v = pyw[(n * 64 + cin) * 9 + tap];
        g_w1h[idx] = __float2half_rn(v);
        return;
    }
    idx -= PREP_A;
    if (idx < PREP_B) {
        int bp = idx % (130 * 130);
        int yy = bp / 130, xx = bp % 130;
        if (yy == 0 || yy == 129 || xx == 0 || xx == 129) {
            uint4* d = (uint4*)(g_h16 + (size_t)idx * 64);
            uint4 z = {0, 0, 0, 0};
#pragma unroll
            for (int i = 0; i < 8; i++) d[i] = z;
        }
        return;
    }
    idx -= PREP_B;
    if (idx < PREP_C) {
        float v0 = q0[idx], v1 = q1[idx];
        __half h0 = __float2half_rn(v0), h1 = __float2half_rn(v1);
        g_wqh[0][idx] = h0; g_wql[0][idx] = __float2half_rn(v0 - __half2float(h0));
        g_wqh[1][idx] = h1; g_wql[1][idx] = __float2half_rn(v1 - __half2float(h1));
        return;
    }
    idx -= PREP_C;
    if (idx < PREP_D) {
        float v0 = p0[idx], v1 = p1[idx];
        __half h0 = __float2half_rn(v0), h1 = __float2half_rn(v1);
        g_wph[0][idx] = h0; g_wpl[0][idx] = __float2half_rn(v0 - __half2float(h0));
        g_wph[1][idx] = h1; g_wpl[1][idx] = __float2half_rn(v1 - __half2float(h1));
    }
}

// ---------------------------------------------------------------------------
// Layer 0 fused gates v2 (unchanged from round 9)
// ---------------------------------------------------------------------------
__global__ __launch_bounds__(256) void layer0_gates(
    const float* __restrict__ x, const float* __restrict__ cw,
    const float* __restrict__ cb, const float* __restrict__ pxw,
    const float* __restrict__ pyw) {
    __shared__ float s_w[64 * 48];
    __shared__ float s_b[3][64];
    __shared__ float s_out[256 * 20];
    int tid = threadIdx.x;
    for (int i = tid; i < 64 * 45; i += 256) {
        int c = i / 45, j = i % 45;
        int g = j / 9, tap = j % 9;
        float v;
        if (g == 0)      v = cw[c * 585 + tap];
        else if (g == 1) v = cw[(128 + c) * 585 + tap];
        else if (g == 2) v = cw[(192 + c) * 585 + tap];
        else if (g == 3) v = pxw[c * 9 + tap];
        else             v = pyw[c * 9 + tap];
        s_w[c * 48 + j] = v;
    }
    if (tid < 64) {
        s_b[0][tid] = cb[tid];
        s_b[1][tid] = cb[128 + tid];
        s_b[2][tid] = cb[192 + tid];
    }
    __syncthreads();

    int p = blockIdx.x * 256 + tid;
    int b = p >> 14, y = (p >> 7) & 127, xc = p & 127;
    float pv[9];
#pragma unroll
    for (int ky = 0; ky < 3; ky++)
#pragma unroll
        for (int kx = 0; kx < 3; kx++) {
            int gy = y + ky - 1, gx = xc + kx - 1;
            pv[ky * 3 + kx] = (gy >= 0 && gy < 128 && gx >= 0 && gx < 128)
                                  ? x[(b << 14) + gy * 128 + gx] : 0.0f;
        }

#pragma unroll 1
    for (int chunk = 0; chunk < 4; chunk++) {
        float4 ov;
#pragma unroll
        for (int cc = 0; cc < 16; cc++) {
            int c = chunk * 16 + cc;
            float wv[48];
            const float4* w4 = (const float4*)(s_w + c * 48);
#pragma unroll
            for (int q = 0; q < 12; q++) {
                float4 t4 = w4[q];
                wv[q * 4 + 0] = t4.x; wv[q * 4 + 1] = t4.y;
                wv[q * 4 + 2] = t4.z; wv[q * 4 + 3] = t4.w;
            }
            float aci = 0.f, aco = 0.f, acg = 0.f, apx = 0.f, apy = 0.f;
#pragma unroll
            for (int tap = 0; tap < 9; tap++) {
                float a = pv[tap];
                aci += a * wv[tap];
                aco += a * wv[9 + tap];
                acg += a * wv[18 + tap];
                apx += a * wv[27 + tap];
                apy += a * wv[36 + tap];
            }
            float ig = sigm(aci + apx + s_b[0][c]);
            float og = sigm(aco + apy + s_b[1][c]);
            float gg = ftanh(acg + apy + s_b[2][c]);
            float r = og * ftanh(ig * gg);
            int e = cc & 3;
            if (e == 0) ov.x = r; else if (e == 1) ov.y = r;
            else if (e == 2) ov.z = r;
            else {
                ov.w = r;
                *(float4*)(s_out + tid * 20 + (cc >> 2) * 4) = ov;
            }
        }
        __syncthreads();
#pragma unroll
        for (int it = 0; it < 4; it++) {
            int i = it * 256 + tid;
            int pp = i >> 2, k = i & 3;
            float4 v4 = *(const float4*)(s_out + pp * 20 + k * 4);
            *(float4*)(g_buf0 +
                       ((size_t)(blockIdx.x * 256 + pp)) * 64 + chunk * 16 + k * 4) = v4;
        }
        __syncthreads();
    }
}

// ---------------------------------------------------------------------------
// Window attention on mma.sync with f16 hi/lo compensation, 8 warps/window.
// Phase1: warp = (colgroup48, mt-half). Phase2: warp = (head, mt-half).
// Phase3: warp = (m-tile, n-half). 2 CTAs/SM.
// ---------------------------------------------------------------------------
#define AT_XH 0
#define AT_XL 8192
#define AT_QH 16384
#define AT_QL 24576
#define AT_KH 32768
#define AT_KL 40960
#define AT_VTH 49152
#define AT_VTL 57344
#define AT_WQH 65536
#define AT_WQL 90112
#define AT_RED 114688
#define AT_SMEM 115200

__global__ __launch_bounds__(256, 2) void win_attn_tc(
    int layer, const float* __restrict__ projb,
    const float* __restrict__ outw, const float* __restrict__ outb,
    float* __restrict__ out, int to_h16) {
    extern __shared__ char smem[];
    u32 sb = smem_u32(smem);
    int tid = threadIdx.x, lane = tid & 31, w = tid >> 5;
    int wid = blockIdx.x;
    int b = wid >> 8, wy = (wid >> 4) & 15, wx = wid & 15;
    int base = ((b * 128 + wy * 8) * 128 + wx * 8) * 64;

    // ---- stage qkv weights hi/lo ----
    if (tid < 192) {
        int r = tid;
        const __half* sh = g_wqh[layer] + r * 64;
        const __half* sl = g_wql[layer] + r * 64;
        u32 row = (u32)r * 128, sw = (u32)((r & 7) << 4);
#pragma unroll
        for (int i = 0; i < 8; i++) {
            cp16(sb + AT_WQH + ((row + i * 16) ^ sw), (const char*)sh + i * 16);
            cp16(sb + AT_WQL + ((row + i * 16) ^ sw), (const char*)sl + i * 16);
        }
    }
    CPASYNC_COMMIT();
    {
        int row = tid >> 2, q = tid & 3;              // token row, 16-col quarter
        int ty = row >> 3, tx = row & 7;
        const float* src = g_buf0 + base + (ty * 128 + tx) * 64 + q * 16;
        u32 sw = (u32)((row & 7) << 4);
#pragma unroll
        for (int j = 0; j < 4; j++) {
            float4 a = *(const float4*)(src + j * 4);
            u32 byte0 = (u32)(row * 128 + q * 32 + j * 8);
            u32 h01, l01, h23, l23;
            split2(a.x, a.y, h01, l01);
            split2(a.z, a.w, h23, l23);
            sts32(sb + AT_XH + (byte0 ^ sw), h01);
            sts32(sb + AT_XL + (byte0 ^ sw), l01);
            sts32(sb + AT_XH + ((byte0 + 4) ^ sw), h23);
            sts32(sb + AT_XL + ((byte0 + 4) ^ sw), l23);
        }
    }
    CPASYNC_WAIT0();
    __syncthreads();

    // lane-invariant ldsm address pieces
    int aRow = (lane & 7) + 8 * ((lane >> 3) & 1);
    u32 aKl = (u32)(16 * (lane >> 4));
    int bRow = ((lane >> 4) & 1) * 8 + (lane & 7);
    u32 bKl = (u32)(((lane >> 3) & 1) * 16);
    int g = lane >> 2, t = lane & 3;

    // ---- phase 1: QKV GEMM (3-term). warp = (ocg, mh): cols [ocg*48,+48),
    //      m-tiles {mh*2, mh*2+1} ----
    {
        int ocg = w >> 1, mh = w & 1;
        float c[2][6][4];
#pragma unroll
        for (int mtl = 0; mtl < 2; mtl++)
#pragma unroll
            for (int nt = 0; nt < 6; nt++)
#pragma unroll
                for (int e = 0; e < 4; e++) c[mtl][nt][e] = 0.0f;

#pragma unroll
        for (int ks = 0; ks < 4; ks++) {
            u32 ah[2][4], al[2][4];
#pragma unroll
            for (int mtl = 0; mtl < 2; mtl++) {
                u32 ar = (u32)((mh * 2 + mtl) * 16 + aRow);
                u32 off = ar * 128 + (u32)(ks * 32) + aKl;
                u32 sw = ((ar & 7) << 4);
                ldsm4(ah[mtl], sb + AT_XH + (off ^ sw));
                ldsm4(al[mtl], sb + AT_XL + (off ^ sw));
            }
#pragma unroll
            for (int np = 0; np < 3; np++) {
                u32 bh[4], bl[4];
                u32 nr = (u32)(ocg * 48 + np * 16 + bRow);
                u32 off = nr * 128 + (u32)(ks * 32) + bKl;
                u32 sw = ((nr & 7) << 4);
                ldsm4(bh, sb + AT_WQH + (off ^ sw));
                ldsm4(bl, sb + AT_WQL + (off ^ sw));
#pragma unroll
                for (int mtl = 0; mtl < 2; mtl++) {
                    mma16816(c[mtl][np * 2], ah[mtl], bh[0], bh[1]);
                    mma16816(c[mtl][np * 2], al[mtl], bh[0], bh[1]);
                    mma16816(c[mtl][np * 2], ah[mtl], bl[0], bl[1]);
                    mma16816(c[mtl][np * 2 + 1], ah[mtl], bh[2], bh[3]);
                    mma16816(c[mtl][np * 2 + 1], al[mtl], bh[2], bh[3]);
                    mma16816(c[mtl][np * 2 + 1], ah[mtl], bl[2], bl[3]);
                }
            }
        }
        // store Q (x0.25), K, V^T as f16 hi/lo
#pragma unroll
        for (int mtl = 0; mtl < 2; mtl++) {
            int mt = mh * 2 + mtl;
#pragma unroll
            for (int nt = 0; nt < 6; nt++) {
                int nc = ocg * 48 + nt * 8 + t * 2;
                int r0 = mt * 16 + g, r1 = r0 + 8;
                float v0 = c[mtl][nt][0], v1 = c[mtl][nt][1];
                float v2 = c[mtl][nt][2], v3 = c[mtl][nt][3];
                u32 sw0 = ((u32)(r0 & 7) << 4), sw1 = ((u32)(r1 & 7) << 4);
                if (nc < 64) {
                    u32 h01, l01, h23, l23;
                    split2(v0 * 0.25f, v1 * 0.25f, h01, l01);
                    split2(v2 * 0.25f, v3 * 0.25f, h23, l23);
                    u32 o0 = ((u32)(r0 * 128 + nc * 2)) ^ sw0;
                    u32 o1 = ((u32)(r1 * 128 + nc * 2)) ^ sw1;
                    sts32(sb + AT_QH + o0, h01); sts32(sb + AT_QL + o0, l01);
                    sts32(sb + AT_QH + o1, h23); sts32(sb + AT_QL + o1, l23);
                } else if (nc < 128) {
                    int kc = nc - 64;
                    u32 h01, l01, h23, l23;
                    split2(v0, v1, h01, l01);
                    split2(v2, v3, h23, l23);
                    u32 o0 = ((u32)(r0 * 128 + kc * 2)) ^ sw0;
                    u32 o1 = ((u32)(r1 * 128 + kc * 2)) ^ sw1;
                    sts32(sb + AT_KH + o0, h01); sts32(sb + AT_KL + o0, l01);
                    sts32(sb + AT_KH + o1, h23); sts32(sb + AT_KL + o1, l23);
                } else {
                    int d0 = nc - 128, d1 = d0 + 1;
                    u32 s0 = (u32)((d0 & 7) << 4), s1 = (u32)((d1 & 7) << 4);
                    float vv[4] = {v0, v1, v2, v3};
                    int dd[4] = {d0, d1, d0, d1};
                    int rr[4] = {r0, r0, r1, r1};
                    u32 ss[4] = {s0, s1, s0, s1};
#pragma unroll
                    for (int e = 0; e < 4; e++) {
                        __half h = __float2half_rn(vv[e]);
                        float rl = vv[e] - __half2float(h);
                        u32 off = ((u32)(dd[e] * 128 + rr[e] * 2)) ^ ss[e];
                        sts16(sb + AT_VTH + off, vv[e]);
                        sts16(sb + AT_VTL + off, rl);
                    }
                }
            }
        }
    }
    __syncthreads();

    // ---- phase 2: attention, warp = (head, mt-half) ----
    {
        int h = w >> 1, mh = w & 1;
        u32 kbh[4][4], kbl[4][4], vbh[4][4], vbl[4][4];
#pragma unroll
        for (int np = 0; np < 4; np++) {
            u32 nr = (u32)(np * 16 + bRow);
            u32 off = nr * 128 + (u32)(h * 32) + bKl;
            u32 sw = ((nr & 7) << 4);
            ldsm4(kbh[np], sb + AT_KH + (off ^ sw));
            ldsm4(kbl[np], sb + AT_KL + (off ^ sw));
        }
#pragma unroll
        for (int ks = 0; ks < 4; ks++) {
            u32 nr = (u32)(h * 16 + bRow);
            u32 off = nr * 128 + (u32)(ks * 32) + bKl;
            u32 sw = ((nr & 7) << 4);
            ldsm4(vbh[ks], sb + AT_VTH + (off ^ sw));
            ldsm4(vbl[ks], sb + AT_VTL + (off ^ sw));
        }
        __syncthreads();   // all warps hold K/V fragments; vt planes now free
        // stage proj weights into the vt planes (overlap with compute)
        if (tid < 128) {
            int r = tid & 63;
            const __half* src = (tid < 64) ? (g_wph[layer] + r * 64)
                                           : (g_wpl[layer] + r * 64);
            u32 dstb = (tid < 64) ? (sb + AT_VTH) : (sb + AT_VTL);
            u32 row = (u32)r * 128, sw = (u32)((r & 7) << 4);
#pragma unroll
            for (int i = 0; i < 8; i++)
                cp16(dstb + ((row + i * 16) ^ sw), (const char*)src + i * 16);
        }
        CPASYNC_COMMIT();

#pragma unroll
        for (int mtl = 0; mtl < 2; mtl++) {
            int mt = mh * 2 + mtl;
            u32 aqh[4], aql[4];
            u32 ar = (u32)(mt * 16 + aRow);
            u32 off = ar * 128 + (u32)(h * 32) + aKl;
            u32 sw = ((ar & 7) << 4);
            ldsm4(aqh, sb + AT_QH + (off ^ sw));
            ldsm4(aql, sb + AT_QL + (off ^ sw));

            float s[8][4];
#pragma unroll
            for (int nt = 0; nt < 8; nt++)
#pragma unroll
                for (int e = 0; e < 4; e++) s[nt][e] = 0.0f;
#pragma unroll
            for (int np = 0; np < 4; np++) {
                mma16816(s[np * 2], aqh, kbh[np][0], kbh[np][1]);
                mma16816(s[np * 2], aql, kbh[np][0], kbh[np][1]);
                mma16816(s[np * 2], aqh, kbl[np][0], kbl[np][1]);
                mma16816(s[np * 2 + 1], aqh, kbh[np][2], kbh[np][3]);
                mma16816(s[np * 2 + 1], aql, kbh[np][2], kbh[np][3]);
                mma16816(s[np * 2 + 1], aqh, kbl[np][2], kbl[np][3]);
            }
            // softmax rows (mt*16+g) and (+8)
            float m0 = -1e30f, m1 = -1e30f;
#pragma unroll
            for (int nt = 0; nt < 8; nt++) {
                m0 = fmaxf(m0, fmaxf(s[nt][0], s[nt][1]));
                m1 = fmaxf(m1, fmaxf(s[nt][2], s[nt][3]));
            }
            m0 = fmaxf(m0, __shfl_xor_sync(0xffffffff, m0, 1));
            m0 = fmaxf(m0, __shfl_xor_sync(0xffffffff, m0, 2));
            m1 = fmaxf(m1, __shfl_xor_sync(0xffffffff, m1, 1));
            m1 = fmaxf(m1, __shfl_xor_sync(0xffffffff, m1, 2));
            float s0 = 0.f, s1 = 0.f;
#pragma unroll
            for (int nt = 0; nt < 8; nt++) {
                s[nt][0] = __expf(s[nt][0] - m0); s0 += s[nt][0];
                s[nt][1] = __expf(s[nt][1] - m0); s0 += s[nt][1];
                s[nt][2] = __expf(s[nt][2] - m1); s1 += s[nt][2];
                s[nt][3] = __expf(s[nt][3] - m1); s1 += s[nt][3];
            }
            s0 += __shfl_xor_sync(0xffffffff, s0, 1);
            s0 += __shfl_xor_sync(0xffffffff, s0, 2);
            s1 += __shfl_xor_sync(0xffffffff, s1, 1);
            s1 += __shfl_xor_sync(0xffffffff, s1, 2);
            float i0 = 1.0f / s0, i1 = 1.0f / s1;

            float o[2][4];
#pragma unroll
            for (int nt = 0; nt < 2; nt++)
#pragma unroll
                for (int e = 0; e < 4; e++) o[nt][e] = 0.0f;
#pragma unroll
            for (int ks = 0; ks < 4; ks++) {
                u32 ph[4], pl[4];
                split2(s[2 * ks][0], s[2 * ks][1], ph[0], pl[0]);
                split2(s[2 * ks][2], s[2 * ks][3], ph[1], pl[1]);
                split2(s[2 * ks + 1][0], s[2 * ks + 1][1], ph[2], pl[2]);
                split2(s[2 * ks + 1][2], s[2 * ks + 1][3], ph[3], pl[3]);
                mma16816(o[0], ph, vbh[ks][0], vbh[ks][1]);
                mma16816(o[0], pl, vbh[ks][0], vbh[ks][1]);
                mma16816(o[0], ph, vbl[ks][0], vbl[ks][1]);
                mma16816(o[1], ph, vbh[ks][2], vbh[ks][3]);
                mma16816(o[1], pl, vbh[ks][2], vbh[ks][3]);
                mma16816(o[1], ph, vbl[ks][2], vbl[ks][3]);
            }
            // scale + store O hi/lo to x planes
            int r0 = mt * 16 + g, r1 = r0 + 8;
            u32 sw0 = ((u32)(r0 & 7) << 4), sw1 = ((u32)(r1 & 7) << 4);
#pragma unroll
            for (int nt = 0; nt < 2; nt++) {
                int dc = h * 16 + nt * 8 + t * 2;
                u32 h01, l01, h23, l23;
                split2(o[nt][0] * i0, o[nt][1] * i0, h01, l01);
                split2(o[nt][2] * i1, o[nt][3] * i1, h23, l23);
                u32 o0 = ((u32)(r0 * 128 + dc * 2)) ^ sw0;
                u32 o1 = ((u32)(r1 * 128 + dc * 2)) ^ sw1;
                sts32(sb + AT_XH + o0, h01); sts32(sb + AT_XL + o0, l01);
                sts32(sb + AT_XH + o1, h23); sts32(sb + AT_XL + o1, l23);
            }
        }
    }
    CPASYNC_WAIT0();
    __syncthreads();

    // ---- phase 3: proj GEMM (3-term), warp = (m-tile, n-half) ----
    {
        int mtile = w >> 1, nh = w & 1;
        float c[4][4];
#pragma unroll
        for (int nt = 0; nt < 4; nt++)
#pragma unroll
            for (int e = 0; e < 4; e++) c[nt][e] = 0.0f;
#pragma unroll
        for (int ks = 0; ks < 4; ks++) {
            u32 ah[4], al[4];
            u32 ar = (u32)(mtile * 16 + aRow);
            u32 off = ar * 128 + (u32)(ks * 32) + aKl;
            u32 sw = ((ar & 7) << 4);
            ldsm4(ah, sb + AT_XH + (off ^ sw));
            ldsm4(al, sb + AT_XL + (off ^ sw));
#pragma unroll
            for (int npl = 0; npl < 2; npl++) {
                int np = nh * 2 + npl;
                u32 bh[4], bl[4];
                u32 nr = (u32)(np * 16 + bRow);
                u32 boff = nr * 128 + (u32)(ks * 32) + bKl;
                u32 bsw = ((nr & 7) << 4);
                ldsm4(bh, sb + AT_VTH + (boff ^ bsw));
                ldsm4(bl, sb + AT_VTL + (boff ^ bsw));
                mma16816(c[npl * 2], ah, bh[0], bh[1]);
                mma16816(c[npl * 2], al, bh[0], bh[1]);
                mma16816(c[npl * 2], ah, bl[0], bl[1]);
                mma16816(c[npl * 2 + 1], ah, bh[2], bh[3]);
                mma16816(c[npl * 2 + 1], al, bh[2], bh[3]);
                mma16816(c[npl * 2 + 1], ah, bl[2], bl[3]);
            }
        }
        if (to_h16) {
            // epilogue: bias + write padded f16
#pragma unroll
            for (int ntl = 0; ntl < 4; ntl++) {
                int nt = nh * 4 + ntl;
                int cc = nt * 8 + t * 2;
                float b0 = __ldg(projb + cc), b1 = __ldg(projb + cc + 1);
#pragma unroll
                for (int rh = 0; rh < 2; rh++) {
                    int tok = mtile * 16 + g + rh * 8;
                    int ty = tok >> 3, tx = tok & 7;
                    float v0 = c[ntl][rh * 2] + b0, v1 = c[ntl][rh * 2 + 1] + b1;
                    int gy = wy * 8 + ty, gx = wx * 8 + tx;
                    __half* dst = g_h16 +
                        ((size_t)((b * 130 + gy + 1) * 130 + gx + 1)) * 64 + cc;
                    *(__half2*)dst = __floats2half2_rn(v0, v1);
                }
            }
        } else {
            // fused 1x1 output conv, split across n-halves
            float* s_red = (float*)(smem + AT_RED);    // [4 mtile][2 nh][8 g][2 rh]
            float acc0 = 0.0f, acc1 = 0.0f;
#pragma unroll
            for (int ntl = 0; ntl < 4; ntl++) {
                int cc = (nh * 4 + ntl) * 8 + t * 2;
                float b0 = __ldg(projb + cc), b1 = __ldg(projb + cc + 1);
                float w0 = __ldg(outw + cc), w1 = __ldg(outw + cc + 1);
                acc0 += (c[ntl][0] + b0) * w0 + (c[ntl][1] + b1) * w1;
                acc1 += (c[ntl][2] + b0) * w0 + (c[ntl][3] + b1) * w1;
            }
            acc0 += __shfl_xor_sync(0xffffffff, acc0, 1);
            acc0 += __shfl_xor_sync(0xffffffff, acc0, 2);
            acc1 += __shfl_xor_sync(0xffffffff, acc1, 1);
            acc1 += __shfl_xor_sync(0xffffffff, acc1, 2);
            if (t == 0) {
                s_red[((mtile * 2 + nh) * 8 + g) * 2 + 0] = acc0;
                s_red[((mtile * 2 + nh) * 8 + g) * 2 + 1] = acc1;
            }
            __syncthreads();
            if (tid < 64) {
                int mt2 = tid >> 4, g2 = (tid >> 1) & 7, rh2 = tid & 1;
                float v = s_red[((mt2 * 2 + 0) * 8 + g2) * 2 + rh2] +
                          s_red[((mt2 * 2 + 1) * 8 + g2) * 2 + rh2] + __ldg(outb);
                int tok = mt2 * 16 + g2 + rh2 * 8;
                int ty = tok >> 3, tx = tok & 7;
                int gy = wy * 8 + ty, gx = wx * 8 + tx;
                out[(b * 128 + gy) * 128 + gx] = v;
            }
        }
    }
}

// ---------------------------------------------------------------------------
// Layer 1 conv on the tensor pipe via mma.sync (unchanged from round 9)
// ---------------------------------------------------------------------------
#define L1_A_OFF 0
#define L1_A_BYTES (390 * 128)
#define L1_B0 L1_A_BYTES
#define L1_B_BYTES (320 * 128)
#define L1_B1 (L1_B0 + L1_B_BYTES)
#define L1_SMEM_TOTAL (L1_B1 + L1_B_BYTES)   // 131840

__device__ __forceinline__ void l1_load_B(u32 sB, int tap, int tid) {
    if (tid < 320) {
        const __half* src = g_w1h + (size_t)(tap * 320 + tid) * 64;
        u32 row = tid * 128;
        u32 sw = (u32)((tid & 7) << 4);
#pragma unroll
        for (int i = 0; i < 8; i++)
            cp16(sB + ((row + i * 16) ^ sw), (const char*)src + i * 16);
    }
}

__global__ __launch_bounds__(512, 1) void layer1_tc(const float* __restrict__ cb) {
    extern __shared__ char smem[];
    u32 sb = smem_u32(smem);
    int tid = threadIdx.x, lane = tid & 31, warp = tid >> 5;
    int wm = warp & 3, wn = warp >> 2;
    int tile = blockIdx.x;
    int b = tile >> 7, y = tile & 127;

    if (tid < 390) {
        int rowIdx = tid / 130, col = tid % 130;
        const __half* src = g_h16 +
            ((size_t)((b * 130 + y + rowIdx) * 130 + col)) * 64;
        u32 row = (u32)tid * 128;
        u32 sw = (u32)((tid & 7) << 4);
#pragma unroll
        for (int i = 0; i < 8; i++)
            cp16(sb + L1_A_OFF + ((row + i * 16) ^ sw), (const char*)src + i * 16);
    }
    l1_load_B(sb + L1_B0, 0, tid);
    CPASYNC_COMMIT();
    CPASYNC_WAIT0();
    __syncthreads();

    float c[2][5][2][4];
#pragma unroll
    for (int mi = 0; mi < 2; mi++)
#pragma unroll
        for (int g5 = 0; g5 < 5; g5++)
#pragma unroll
            for (int nt = 0; nt < 2; nt++)
#pragma unroll
                for (int e = 0; e < 4; e++) c[mi][g5][nt][e] = 0.0f;

    int arow = wm * 32 + (lane & 7) + 8 * ((lane >> 3) & 1);
    u32 aklane = (u32)(16 * (lane >> 4));
    u32 bkl = (u32)(((lane >> 3) & 1) * 16);
    int bnrow_base = wn * 16 + ((lane >> 4) & 1) * 8 + (lane & 7);
    u32 bswz = (u32)((lane & 7) << 4);

#pragma unroll 1
    for (int tap = 0; tap < 9; tap++) {
        u32 Bb = sb + ((tap & 1) ? L1_B1 : L1_B0);
        if (tap < 8) {
            l1_load_B(sb + ((tap & 1) ? L1_B0 : L1_B1), tap + 1, tid);
            CPASYNC_COMMIT();
        }
        int dy = tap / 3, dx = tap % 3;
        int br0 = dy * 130 + arow + dx;
#pragma unroll
        for (int ks = 0; ks < 4; ks++) {
            u32 a[2][4];
#pragma unroll
            for (int mi = 0; mi < 2; mi++) {
                u32 br = (u32)(br0 + mi * 16);
                u32 off = br * 128 + (u32)(ks * 32) + aklane;
                ldsm4(a[mi], sb + L1_A_OFF + (off ^ ((br & 7) << 4)));
            }
#pragma unroll
            for (int g5 = 0; g5 < 5; g5++) {
                u32 bfr[4];
                u32 nrow = (u32)(g5 * 64 + bnrow_base);
                u32 off = nrow * 128 + (u32)(ks * 32) + bkl;
                ldsm4(bfr, Bb + (off ^ bswz));
#pragma unroll
                for (int mi = 0; mi < 2; mi++) {
                    mma16816(c[mi][g5][0], a[mi], bfr[0], bfr[1]);
                    mma16816(c[mi][g5][1], a[mi], bfr[2], bfr[3]);
                }
            }
        }
        if (tap < 8) { CPASYNC_WAIT0(); }
        __syncthreads();
    }

    int q = lane & 3, gr = lane >> 2;
    int ocB = wn * 16;
#pragma unroll
    for (int mi = 0; mi < 2; mi++) {
#pragma unroll
        for (int rh = 0; rh < 2; rh++) {
            int x = wm * 32 + mi * 16 + gr + rh * 8;
            float* orow = g_buf0 + ((size_t)((b * 128 + y) * 128 + x)) * 64;
#pragma unroll
            for (int nt = 0; nt < 2; nt++) {
#pragma unroll
                for (int e = 0; e < 2; e++) {
                    int oc = ocB + nt * 8 + q * 2 + e;
                    int ai = rh * 2 + e;
                    float ci = c[mi][0][nt][ai];
                    float co = c[mi][1][nt][ai];
                    float cg = c[mi][2][nt][ai];
                    float px = c[mi][3][nt][ai];
                    float py = c[mi][4][nt][ai];
                    float ig = sigm(ci + px + __ldg(cb + oc));
                    float og = sigm(co + py + __ldg(cb + 128 + oc));
                    float gg = ftanh(cg + py + __ldg(cb + 192 + oc));
                    orow[oc] = og * ftanh(ig * gg);
                }
            }
        }
    }
}

// ---------------------------------------------------------------------------
extern "C" void kernel_launch(void* const* d_in, const int* in_sizes, int n_in,
                              void* d_out, int out_size) {
    const float* x      = (const float*)d_in[0];
    const float* cw0    = (const float*)d_in[1];
    const float* cb0    = (const float*)d_in[2];
    const float* pxw0   = (const float*)d_in[3];
    const float* pyw0   = (const float*)d_in[4];
    const float* qkvw0  = (const float*)d_in[5];
    const float* projw0 = (const float*)d_in[6];
    const float* projb0 = (const float*)d_in[7];
    const float* cw1    = (const float*)d_in[8];
    const float* cb1    = (const float*)d_in[9];
    const float* pxw1   = (const float*)d_in[10];
    const float* pyw1   = (const float*)d_in[11];
    const float* qkvw1  = (const float*)d_in[12];
    const float* projw1 = (const float*)d_in[13];
    const float* projb1 = (const float*)d_in[14];
    const float* outw   = (const float*)d_in[15];
    const float* outb   = (const float*)d_in[16];
    float* out = (float*)d_out;

    cudaFuncSetAttribute(win_attn_tc, cudaFuncAttributeMaxDynamicSharedMemorySize,
                         AT_SMEM);
    cudaFuncSetAttribute(layer1_tc, cudaFuncAttributeMaxDynamicSharedMemorySize,
                         L1_SMEM_TOTAL);

    prep_all<<<(PREP_TOTAL + 255) / 256, 256>>>(cw1, pxw1, pyw1,
                                                qkvw0, projw0, qkvw1, projw1);
    layer0_gates<<<1024, 256>>>(x, cw0, cb0, pxw0, pyw0);             // -> buf0
    win_attn_tc<<<4096, 256, AT_SMEM>>>(0, projb0, outw, outb, out, 1); // buf0 -> h16
    layer1_tc<<<2048, 512, L1_SMEM_TOTAL>>>(cb1);                     // h16 -> buf0
    win_attn_tc<<<4096, 256, AT_SMEM>>>(1, projb1, outw, outb, out, 0); // buf0 -> out
}